// round 6
// baseline (speedup 1.0000x reference)
#include <cuda_runtime.h>
#include <cuda_bf16.h>
#include <math.h>
#include <stdint.h>

// Model dims
#define BB   2
#define TT   1024
#define DD   1024
#define HH   16
#define HDIM 64
#define LL   8
#define VV   32000
#define MM   (BB*TT)   // 2048 tokens

typedef __nv_bfloat16 bf16;
typedef __nv_bfloat162 bf162;

// GEMM tiling: CTA 128x256, warp 64x64, BK=32
#define BM 128
#define BN 256
#define BK 32
#define LDP 40                       // smem row stride in bf16
#define A_ELE (BM*LDP)               // 5120
#define B_ELE (BN*LDP)               // 10240
#define BUF_ELE (2*A_ELE + 2*B_ELE)  // 30720 bf16 per buffer
#define GSM (2 * BUF_ELE * 2)        // 122880 bytes

// fp32 scratch
__device__ float g_x  [MM * DD];
__device__ float g_qkv[MM * 3 * DD];
// bf16 hi/lo activation scratch
__device__ bf16 g_h_hi[MM * DD],     g_h_lo[MM * DD];
__device__ bf16 g_y_hi[MM * DD],     g_y_lo[MM * DD];
__device__ bf16 g_g_hi[MM * 4 * DD], g_g_lo[MM * 4 * DD];
// bf16 hi/lo weight scratch
__device__ bf16 g_qkvw_hi[LL * 3 * DD * DD], g_qkvw_lo[LL * 3 * DD * DD];
__device__ bf16 g_projw_hi[LL * DD * DD],    g_projw_lo[LL * DD * DD];
__device__ bf16 g_fcw_hi [LL * 4 * DD * DD], g_fcw_lo [LL * 4 * DD * DD];
__device__ bf16 g_fc2w_hi[LL * 4 * DD * DD], g_fc2w_lo[LL * 4 * DD * DD];
__device__ bf16 g_lmw_hi [VV * DD],          g_lmw_lo [VV * DD];

// ---------------------------------------------------------------------------
// Fused weight split: one launch, blockIdx.y selects the array
// ---------------------------------------------------------------------------
__global__ void wsplit_all(const float* s0, bf16* h0, bf16* l0, int n0,
                           const float* s1, bf16* h1, bf16* l1, int n1,
                           const float* s2, bf16* h2, bf16* l2, int n2,
                           const float* s3, bf16* h3, bf16* l3, int n3,
                           const float* s4, bf16* h4, bf16* l4, int n4) {
    const float* src; bf16* hi; bf16* lo; int n;
    switch (blockIdx.y) {
        case 0: src = s0; hi = h0; lo = l0; n = n0; break;
        case 1: src = s1; hi = h1; lo = l1; n = n1; break;
        case 2: src = s2; hi = h2; lo = l2; n = n2; break;
        case 3: src = s3; hi = h3; lo = l3; n = n3; break;
        default: src = s4; hi = h4; lo = l4; n = n4; break;
    }
    int i = (blockIdx.x * blockDim.x + threadIdx.x) * 4;
    if (i >= n) return;
    float4 v = *(const float4*)(src + i);
    bf16 a0 = __float2bfloat16(v.x), a1 = __float2bfloat16(v.y);
    bf16 a2 = __float2bfloat16(v.z), a3 = __float2bfloat16(v.w);
    bf162 p;
    p.x = a0; p.y = a1; ((bf162*)(hi + i))[0] = p;
    p.x = a2; p.y = a3; ((bf162*)(hi + i))[1] = p;
    p.x = __float2bfloat16(v.x - __bfloat162float(a0));
    p.y = __float2bfloat16(v.y - __bfloat162float(a1));
    ((bf162*)(lo + i))[0] = p;
    p.x = __float2bfloat16(v.z - __bfloat162float(a2));
    p.y = __float2bfloat16(v.w - __bfloat162float(a3));
    ((bf162*)(lo + i))[1] = p;
}

// ---------------------------------------------------------------------------
// Embedding
// ---------------------------------------------------------------------------
__global__ void embed_kernel(const int* __restrict__ idx,
                             const float* __restrict__ wte,
                             const float* __restrict__ wpe,
                             float* __restrict__ x) {
    int token = blockIdx.x;
    int t = token % TT;
    int id = idx[token];
    const float4* src = (const float4*)(wte + (size_t)id * DD);
    const float4* pos = (const float4*)(wpe + (size_t)t * DD);
    float4* dst = (float4*)(x + (size_t)token * DD);
    for (int i = threadIdx.x; i < DD / 4; i += blockDim.x) {
        float4 a = src[i], b = pos[i];
        dst[i] = make_float4(a.x + b.x, a.y + b.y, a.z + b.z, a.w + b.w);
    }
}

// ---------------------------------------------------------------------------
// LayerNorm over D=1024, writing bf16 hi/lo split output
// ---------------------------------------------------------------------------
__global__ __launch_bounds__(256) void ln_split_kernel(const float* __restrict__ x,
                                                       const float* __restrict__ sc,
                                                       const float* __restrict__ bi,
                                                       bf16* __restrict__ ohi,
                                                       bf16* __restrict__ olo) {
    int token = blockIdx.x;
    const float4* xp = (const float4*)(x + (size_t)token * DD);
    float4 v = xp[threadIdx.x];
    float s = v.x + v.y + v.z + v.w;
    float q = v.x * v.x + v.y * v.y + v.z * v.z + v.w * v.w;
#pragma unroll
    for (int o = 16; o; o >>= 1) {
        s += __shfl_xor_sync(0xffffffffu, s, o);
        q += __shfl_xor_sync(0xffffffffu, q, o);
    }
    __shared__ float ss[8], sq[8];
    int w = threadIdx.x >> 5, l = threadIdx.x & 31;
    if (l == 0) { ss[w] = s; sq[w] = q; }
    __syncthreads();
    if (w == 0) {
        s = (l < 8) ? ss[l] : 0.f;
        q = (l < 8) ? sq[l] : 0.f;
#pragma unroll
        for (int o = 4; o; o >>= 1) {
            s += __shfl_xor_sync(0xffffffffu, s, o);
            q += __shfl_xor_sync(0xffffffffu, q, o);
        }
        if (l == 0) { ss[0] = s; sq[0] = q; }
    }
    __syncthreads();
    float mu  = ss[0] * (1.f / DD);
    float var = sq[0] * (1.f / DD) - mu * mu;
    float inv = rsqrtf(var + 1e-5f);
    float4 sv = ((const float4*)sc)[threadIdx.x];
    float4 bv = ((const float4*)bi)[threadIdx.x];
    float r0 = (v.x - mu) * inv * sv.x + bv.x;
    float r1 = (v.y - mu) * inv * sv.y + bv.y;
    float r2 = (v.z - mu) * inv * sv.z + bv.z;
    float r3 = (v.w - mu) * inv * sv.w + bv.w;
    size_t o = (size_t)token * DD + threadIdx.x * 4;
    bf16 h0 = __float2bfloat16(r0), h1 = __float2bfloat16(r1);
    bf16 h2 = __float2bfloat16(r2), h3 = __float2bfloat16(r3);
    bf162 p;
    p.x = h0; p.y = h1; ((bf162*)(ohi + o))[0] = p;
    p.x = h2; p.y = h3; ((bf162*)(ohi + o))[1] = p;
    p.x = __float2bfloat16(r0 - __bfloat162float(h0));
    p.y = __float2bfloat16(r1 - __bfloat162float(h1));
    ((bf162*)(olo + o))[0] = p;
    p.x = __float2bfloat16(r2 - __bfloat162float(h2));
    p.y = __float2bfloat16(r3 - __bfloat162float(h3));
    ((bf162*)(olo + o))[1] = p;
}

// ---------------------------------------------------------------------------
// Tensor-core GEMM NT, bf16-split 3-pass, CTA 128x256, warp 64x64.
// C[m,n] = sum_k A[m,k]*B[n,k]. cp.async double-buffered.
// ---------------------------------------------------------------------------
#define FLAG_BIAS  1
#define FLAG_RES   2
#define FLAG_GELU  4
#define FLAG_SPLIT 8

__device__ __forceinline__ float gelu_exact(float v) {
    return 0.5f * v * (1.f + erff(v * 0.70710678118654752f));
}

__device__ __forceinline__ void ldm_x4(uint32_t& r0, uint32_t& r1, uint32_t& r2, uint32_t& r3,
                                       uint32_t addr) {
    asm volatile("ldmatrix.sync.aligned.m8n8.x4.shared.b16 {%0,%1,%2,%3}, [%4];\n"
                 : "=r"(r0), "=r"(r1), "=r"(r2), "=r"(r3) : "r"(addr));
}

__device__ __forceinline__ void mma16816(float* d, const uint32_t* a, const uint32_t* b) {
    asm volatile(
        "mma.sync.aligned.m16n8k16.row.col.f32.bf16.bf16.f32 "
        "{%0,%1,%2,%3}, {%4,%5,%6,%7}, {%8,%9}, {%0,%1,%2,%3};\n"
        : "+f"(d[0]), "+f"(d[1]), "+f"(d[2]), "+f"(d[3])
        : "r"(a[0]), "r"(a[1]), "r"(a[2]), "r"(a[3]), "r"(b[0]), "r"(b[1]));
}

__device__ __forceinline__ void cp16(uint32_t dst, const void* src) {
    asm volatile("cp.async.cg.shared.global [%0], [%1], 16;\n" :: "r"(dst), "l"(src));
}

__global__ __launch_bounds__(256) void gemm3(const bf16* __restrict__ Ah,
                                             const bf16* __restrict__ Al,
                                             const bf16* __restrict__ Bh,
                                             const bf16* __restrict__ Bl,
                                             const float* __restrict__ bias,
                                             const float* res,
                                             float* C, bf16* Chi, bf16* Clo,
                                             int M, int N, int K, int flags) {
    extern __shared__ __align__(16) bf16 sm[];
    int tid = threadIdx.x;
    int warp = tid >> 5, lane = tid & 31;
    int bm = blockIdx.y * BM, bn = blockIdx.x * BN;
    int wm = (warp >> 2) * 64;      // 0/64
    int wn = (warp & 3) * 64;       // 0/64/128/192

    uint32_t smbase = (uint32_t)__cvta_generic_to_shared(sm);

    float acc[4][8][4];
#pragma unroll
    for (int i = 0; i < 4; i++)
#pragma unroll
        for (int j = 0; j < 8; j++)
#pragma unroll
            for (int r = 0; r < 4; r++) acc[i][j][r] = 0.f;

    // ldmatrix lane addressing
    int a_r = ((lane >> 3) & 1) * 8 + (lane & 7);
    int a_c = (lane >> 4) * 8;
    int b_r = (lane >> 4) * 8 + (lane & 7);
    int b_c = ((lane >> 3) & 1) * 8;

    const bf16* srcA[2] = { Ah + (size_t)bm * K, Al + (size_t)bm * K };
    const bf16* srcB[2] = { Bh + (size_t)bn * K, Bl + (size_t)bn * K };

    // cp.async staging: 3072 x 16B chunks per buffer
    //   chunks [0,512) Ah, [512,1024) Al, [1024,2048) Bh, [2048,3072) Bl
    auto stage = [&](int buf, int k0) {
        uint32_t bufoff = (uint32_t)(buf * BUF_ELE) * 2;
#pragma unroll
        for (int i = 0; i < 12; i++) {
            int cid = tid + i * 256;
            int isB = cid >= 1024;
            int local = isB ? cid - 1024 : cid;
            int which = isB ? (local >> 10) : (local >> 9);   // hi=0/lo=1
            int sub = isB ? (local & 1023) : (local & 511);
            int row = sub >> 2;
            int col = (sub & 3) * 8;
            const bf16* src = (isB ? srcB[which] : srcA[which]) + (size_t)row * K + k0 + col;
            uint32_t ele = isB ? (2 * A_ELE + which * B_ELE) : (which * A_ELE);
            uint32_t dst = smbase + bufoff + (ele + row * LDP + col) * 2;
            cp16(dst, src);
        }
        asm volatile("cp.async.commit_group;\n");
    };

    stage(0, 0);
    int buf = 0;
    for (int k0 = 0; k0 < K; k0 += BK) {
        if (k0 + BK < K) {
            stage(buf ^ 1, k0 + BK);
            asm volatile("cp.async.wait_group 1;\n");
        } else {
            asm volatile("cp.async.wait_group 0;\n");
        }
        __syncthreads();

        uint32_t base = smbase + (uint32_t)(buf * BUF_ELE) * 2;
        uint32_t offAh = base;
        uint32_t offAl = base + (uint32_t)A_ELE * 2;
        uint32_t offBh = base + (uint32_t)(2 * A_ELE) * 2;
        uint32_t offBl = offBh + (uint32_t)B_ELE * 2;

#pragma unroll
        for (int ks = 0; ks < BK; ks += 16) {
            uint32_t ah[4][4], al[4][4], bh[8][2], bl[8][2];
#pragma unroll
            for (int mf = 0; mf < 4; mf++) {
                uint32_t addr = offAh + (uint32_t)((wm + mf * 16 + a_r) * LDP + ks + a_c) * 2;
                ldm_x4(ah[mf][0], ah[mf][1], ah[mf][2], ah[mf][3], addr);
            }
#pragma unroll
            for (int p = 0; p < 4; p++) {
                uint32_t addr = offBh + (uint32_t)((wn + p * 16 + b_r) * LDP + ks + b_c) * 2;
                uint32_t r0, r1, r2, r3;
                ldm_x4(r0, r1, r2, r3, addr);
                bh[2 * p][0] = r0; bh[2 * p][1] = r1;
                bh[2 * p + 1][0] = r2; bh[2 * p + 1][1] = r3;
            }
#pragma unroll
            for (int mf = 0; mf < 4; mf++)
#pragma unroll
                for (int nf = 0; nf < 8; nf++)
                    mma16816(acc[mf][nf], ah[mf], bh[nf]);

#pragma unroll
            for (int p = 0; p < 4; p++) {
                uint32_t addr = offBl + (uint32_t)((wn + p * 16 + b_r) * LDP + ks + b_c) * 2;
                uint32_t r0, r1, r2, r3;
                ldm_x4(r0, r1, r2, r3, addr);
                bl[2 * p][0] = r0; bl[2 * p][1] = r1;
                bl[2 * p + 1][0] = r2; bl[2 * p + 1][1] = r3;
            }
#pragma unroll
            for (int mf = 0; mf < 4; mf++)
#pragma unroll
                for (int nf = 0; nf < 8; nf++)
                    mma16816(acc[mf][nf], ah[mf], bl[nf]);

#pragma unroll
            for (int mf = 0; mf < 4; mf++) {
                uint32_t addr = offAl + (uint32_t)((wm + mf * 16 + a_r) * LDP + ks + a_c) * 2;
                ldm_x4(al[mf][0], al[mf][1], al[mf][2], al[mf][3], addr);
            }
#pragma unroll
            for (int mf = 0; mf < 4; mf++)
#pragma unroll
                for (int nf = 0; nf < 8; nf++)
                    mma16816(acc[mf][nf], al[mf], bh[nf]);
        }
        __syncthreads();
        buf ^= 1;
    }

    // epilogue
    int gid = lane >> 2, tg = lane & 3;
#pragma unroll
    for (int mf = 0; mf < 4; mf++) {
#pragma unroll
        for (int half = 0; half < 2; half++) {
            int row = bm + wm + mf * 16 + half * 8 + gid;
#pragma unroll
            for (int nf = 0; nf < 8; nf++) {
                int col = bn + wn + nf * 8 + tg * 2;
                float2 o;
                o.x = acc[mf][nf][half * 2 + 0];
                o.y = acc[mf][nf][half * 2 + 1];
                if (flags & FLAG_BIAS) { o.x += bias[col]; o.y += bias[col + 1]; }
                if (flags & FLAG_GELU) { o.x = gelu_exact(o.x); o.y = gelu_exact(o.y); }
                if (flags & FLAG_RES) {
                    float2 r = *(const float2*)(res + (size_t)row * N + col);
                    o.x += r.x; o.y += r.y;
                }
                if (flags & FLAG_SPLIT) {
                    size_t off = (size_t)row * N + col;
                    bf16 h0 = __float2bfloat16(o.x), h1 = __float2bfloat16(o.y);
                    bf162 hp; hp.x = h0; hp.y = h1;
                    *(bf162*)(Chi + off) = hp;
                    bf162 lp;
                    lp.x = __float2bfloat16(o.x - __bfloat162float(h0));
                    lp.y = __float2bfloat16(o.y - __bfloat162float(h1));
                    *(bf162*)(Clo + off) = lp;
                } else {
                    *(float2*)(C + (size_t)row * N + col) = o;
                }
            }
        }
    }
}

// ---------------------------------------------------------------------------
// Causal attention (flash-style). 64 queries/block, 8 warps, 8 queries/warp.
// ---------------------------------------------------------------------------
__global__ __launch_bounds__(256) void attn_kernel(const float* __restrict__ qkv,
                                                   bf16* __restrict__ yhi,
                                                   bf16* __restrict__ ylo) {
    int b = blockIdx.z, h = blockIdx.y, bx = blockIdx.x;
    int tid = threadIdx.x;
    int warp = tid >> 5, lane = tid & 31;
    int q0g = bx * 64 + warp * 8;
    int w8 = warp * 8;

    __shared__ float q_s[64][66];
    __shared__ float k_s[32][66];
    __shared__ float v_s[32][66];

#pragma unroll
    for (int i = 0; i < 8; i++) {
        int cid = tid + i * 256;
        int row = cid >> 5, c2 = cid & 31;
        const float* qp = qkv + (size_t)(b * TT + bx * 64 + row) * (3 * DD) + h * HDIM;
        float2 qv = *(const float2*)(qp + c2 * 2);
        q_s[row][c2 * 2]     = qv.x * 0.125f;
        q_s[row][c2 * 2 + 1] = qv.y * 0.125f;
    }

    float m[8], l[8], accx[8], accy[8];
#pragma unroll
    for (int q = 0; q < 8; q++) { m[q] = -INFINITY; l[q] = 0.f; accx[q] = 0.f; accy[q] = 0.f; }

    int ntiles = bx * 2 + 2;
    const float* kb = qkv + (size_t)(b * TT) * (3 * DD) + DD + h * HDIM;
    const float* vb = kb + DD;

    for (int tile = 0; tile < ntiles; tile++) {
        int kt = tile * 32;
        __syncthreads();
#pragma unroll
        for (int i = 0; i < 8; i++) {
            int cid = tid + i * 256;
            int which = cid >> 10, r = (cid >> 5) & 31, c2 = cid & 31;
            const float* src = (which ? vb : kb) + (size_t)(kt + r) * (3 * DD) + c2 * 2;
            float2 v2 = *(const float2*)src;
            if (which) { v_s[r][c2 * 2] = v2.x; v_s[r][c2 * 2 + 1] = v2.y; }
            else       { k_s[r][c2 * 2] = v2.x; k_s[r][c2 * 2 + 1] = v2.y; }
        }
        __syncthreads();

        if (kt <= q0g + 7) {
            float s[8];
#pragma unroll
            for (int q = 0; q < 8; q++) s[q] = 0.f;
#pragma unroll
            for (int d2 = 0; d2 < 32; d2++) {
                float2 kk = *(const float2*)&k_s[lane][d2 * 2];
#pragma unroll
                for (int q = 0; q < 8; q++) {
                    float2 qq = *(const float2*)&q_s[w8 + q][d2 * 2];
                    s[q] = fmaf(qq.x, kk.x, s[q]);
                    s[q] = fmaf(qq.y, kk.y, s[q]);
                }
            }
            int key = kt + lane;
#pragma unroll
            for (int q = 0; q < 8; q++) {
                if (key > q0g + q) s[q] = -INFINITY;
                float tm = s[q];
#pragma unroll
                for (int o = 16; o; o >>= 1) tm = fmaxf(tm, __shfl_xor_sync(0xffffffffu, tm, o));
                float mn = fmaxf(m[q], tm);
                float corr = __expf(m[q] - mn);
                float p = __expf(s[q] - mn);
                float ps = p;
#pragma unroll
                for (int o = 16; o; o >>= 1) ps += __shfl_xor_sync(0xffffffffu, ps, o);
                l[q] = l[q] * corr + ps;
                accx[q] *= corr; accy[q] *= corr;
                m[q] = mn;
                s[q] = p;
            }
#pragma unroll
            for (int j = 0; j < 32; j++) {
                float2 vv = *(const float2*)&v_s[j][lane * 2];
#pragma unroll
                for (int q = 0; q < 8; q++) {
                    float pj = __shfl_sync(0xffffffffu, s[q], j);
                    accx[q] = fmaf(pj, vv.x, accx[q]);
                    accy[q] = fmaf(pj, vv.y, accy[q]);
                }
            }
        }
    }

#pragma unroll
    for (int q = 0; q < 8; q++) {
        float inv = 1.f / l[q];
        float ox = accx[q] * inv, oy = accy[q] * inv;
        size_t off = (size_t)(b * TT + q0g + q) * DD + h * HDIM + lane * 2;
        bf16 h0 = __float2bfloat16(ox), h1 = __float2bfloat16(oy);
        bf162 hp; hp.x = h0; hp.y = h1;
        *(bf162*)(yhi + off) = hp;
        bf162 lp;
        lp.x = __float2bfloat16(ox - __bfloat162float(h0));
        lp.y = __float2bfloat16(oy - __bfloat162float(h1));
        *(bf162*)(ylo + off) = lp;
    }
}

// ---------------------------------------------------------------------------
// Host launcher
// ---------------------------------------------------------------------------
extern "C" void kernel_launch(void* const* d_in, const int* in_sizes, int n_in,
                              void* d_out, int out_size) {
    const int*   idx    = (const int*)  d_in[0];
    const float* wte    = (const float*)d_in[1];
    const float* wpe    = (const float*)d_in[2];
    const float* ln1_s  = (const float*)d_in[3];
    const float* ln1_b  = (const float*)d_in[4];
    const float* qkv_w  = (const float*)d_in[5];
    const float* proj_w = (const float*)d_in[6];
    const float* ln2_s  = (const float*)d_in[7];
    const float* ln2_b  = (const float*)d_in[8];
    const float* fc_w   = (const float*)d_in[9];
    const float* fc_b   = (const float*)d_in[10];
    const float* fc2_w  = (const float*)d_in[11];
    const float* fc2_b  = (const float*)d_in[12];
    const float* lnf_s  = (const float*)d_in[13];
    const float* lnf_b  = (const float*)d_in[14];
    const float* lm_w   = (const float*)d_in[15];
    float* out = (float*)d_out;

    float *x, *qkv;
    bf16 *h_hi, *h_lo, *y_hi, *y_lo, *gg_hi, *gg_lo;
    bf16 *qw_hi, *qw_lo, *pw_hi, *pw_lo, *fw_hi, *fw_lo, *f2_hi, *f2_lo, *lw_hi, *lw_lo;
    cudaGetSymbolAddress((void**)&x,     g_x);
    cudaGetSymbolAddress((void**)&qkv,   g_qkv);
    cudaGetSymbolAddress((void**)&h_hi,  g_h_hi);   cudaGetSymbolAddress((void**)&h_lo,  g_h_lo);
    cudaGetSymbolAddress((void**)&y_hi,  g_y_hi);   cudaGetSymbolAddress((void**)&y_lo,  g_y_lo);
    cudaGetSymbolAddress((void**)&gg_hi, g_g_hi);   cudaGetSymbolAddress((void**)&gg_lo, g_g_lo);
    cudaGetSymbolAddress((void**)&qw_hi, g_qkvw_hi); cudaGetSymbolAddress((void**)&qw_lo, g_qkvw_lo);
    cudaGetSymbolAddress((void**)&pw_hi, g_projw_hi); cudaGetSymbolAddress((void**)&pw_lo, g_projw_lo);
    cudaGetSymbolAddress((void**)&fw_hi, g_fcw_hi);  cudaGetSymbolAddress((void**)&fw_lo, g_fcw_lo);
    cudaGetSymbolAddress((void**)&f2_hi, g_fc2w_hi); cudaGetSymbolAddress((void**)&f2_lo, g_fc2w_lo);
    cudaGetSymbolAddress((void**)&lw_hi, g_lmw_hi);  cudaGetSymbolAddress((void**)&lw_lo, g_lmw_lo);

    cudaFuncSetAttribute(gemm3, cudaFuncAttributeMaxDynamicSharedMemorySize, GSM);

    embed_kernel<<<MM, 256>>>(idx, wte, wpe, x);

    // one fused weight-split launch (5 arrays via gridDim.y)
    {
        int nq = LL * 3 * DD * DD, np = LL * DD * DD;
        int nf = LL * 4 * DD * DD, n2 = LL * 4 * DD * DD, nl = VV * DD;
        int maxn = nf;  // largest
        dim3 grid((maxn / 4 + 255) / 256, 5);
        wsplit_all<<<grid, 256>>>(qkv_w,  qw_hi, qw_lo, nq,
                                  proj_w, pw_hi, pw_lo, np,
                                  fc_w,   fw_hi, fw_lo, nf,
                                  fc2_w,  f2_hi, f2_lo, n2,
                                  lm_w,   lw_hi, lw_lo, nl);
    }

    for (int l = 0; l < LL; l++) {
        bf16* qwh = qw_hi + (size_t)l * 3 * DD * DD;  bf16* qwl = qw_lo + (size_t)l * 3 * DD * DD;
        bf16* pwh = pw_hi + (size_t)l * DD * DD;      bf16* pwl = pw_lo + (size_t)l * DD * DD;
        bf16* fwh = fw_hi + (size_t)l * 4 * DD * DD;  bf16* fwl = fw_lo + (size_t)l * 4 * DD * DD;
        bf16* f2h = f2_hi + (size_t)l * 4 * DD * DD;  bf16* f2l = f2_lo + (size_t)l * 4 * DD * DD;
        const float* fb  = fc_b  + (size_t)l * 4 * DD;
        const float* f2b = fc2_b + (size_t)l * DD;

        ln_split_kernel<<<MM, 256>>>(x, ln1_s + l * DD, ln1_b + l * DD, h_hi, h_lo);
        gemm3<<<dim3(3 * DD / BN, MM / BM), 256, GSM>>>(h_hi, h_lo, qwh, qwl,
            nullptr, nullptr, qkv, nullptr, nullptr, MM, 3 * DD, DD, 0);
        attn_kernel<<<dim3(TT / 64, HH, BB), 256>>>(qkv, y_hi, y_lo);
        gemm3<<<dim3(DD / BN, MM / BM), 256, GSM>>>(y_hi, y_lo, pwh, pwl,
            nullptr, x, x, nullptr, nullptr, MM, DD, DD, FLAG_RES);
        ln_split_kernel<<<MM, 256>>>(x, ln2_s + l * DD, ln2_b + l * DD, h_hi, h_lo);
        gemm3<<<dim3(4 * DD / BN, MM / BM), 256, GSM>>>(h_hi, h_lo, fwh, fwl,
            fb, nullptr, nullptr, gg_hi, gg_lo, MM, 4 * DD, DD, FLAG_BIAS | FLAG_GELU | FLAG_SPLIT);
        gemm3<<<dim3(DD / BN, MM / BM), 256, GSM>>>(gg_hi, gg_lo, f2h, f2l,
            f2b, x, x, nullptr, nullptr, MM, DD, 4 * DD, FLAG_BIAS | FLAG_RES);
    }

    ln_split_kernel<<<MM, 256>>>(x, lnf_s, lnf_b, h_hi, h_lo);
    gemm3<<<dim3(VV / BN, MM / BM), 256, GSM>>>(h_hi, h_lo, lw_hi, lw_lo,
        nullptr, nullptr, out, nullptr, nullptr, MM, VV, DD, 0);
}

// round 7
// speedup vs baseline: 1.5531x; 1.5531x over previous
#include <cuda_runtime.h>
#include <cuda_bf16.h>
#include <math.h>
#include <stdint.h>

// Model dims
#define BB   2
#define TT   1024
#define DD   1024
#define HH   16
#define HDIM 64
#define LL   8
#define VV   32000
#define MM   (BB*TT)   // 2048 tokens

typedef __nv_bfloat16 bf16;
typedef __nv_bfloat162 bf162;

// GEMM tiling (R4 config)
#define BM 128
#define BN 128
#define BK 32
#define LDP 40           // smem row stride in bf16 (pad 32 -> 40)
#define BUFSZ (4*BM*LDP) // bf16 elems per pipeline buffer
#define GSM (2 * BUFSZ * 2)

// Attention tiling
#define AQ  128          // queries per block (8 warps x 16)
#define AKT 64           // keys per tile
#define LDV 72           // smem row stride (64 + 8)
#define NEGINF (-1e30f)

// fp32 scratch
__device__ float g_x  [MM * DD];
__device__ float g_qkv[MM * 3 * DD];
// bf16 hi/lo activation scratch
__device__ bf16 g_h_hi[MM * DD],     g_h_lo[MM * DD];
__device__ bf16 g_y_hi[MM * DD],     g_y_lo[MM * DD];
__device__ bf16 g_g_hi[MM * 4 * DD], g_g_lo[MM * 4 * DD];
// bf16 hi/lo weight scratch
__device__ bf16 g_qkvw_hi[LL * 3 * DD * DD], g_qkvw_lo[LL * 3 * DD * DD];
__device__ bf16 g_projw_hi[LL * DD * DD],    g_projw_lo[LL * DD * DD];
__device__ bf16 g_fcw_hi [LL * 4 * DD * DD], g_fcw_lo [LL * 4 * DD * DD];
__device__ bf16 g_fc2w_hi[LL * 4 * DD * DD], g_fc2w_lo[LL * 4 * DD * DD];
__device__ bf16 g_lmw_hi [VV * DD],          g_lmw_lo [VV * DD];

// ---------------------------------------------------------------------------
// Small helpers
// ---------------------------------------------------------------------------
__device__ __forceinline__ void split2u(float x, float y, uint32_t& hi, uint32_t& lo) {
    bf162 hp, lp;
    hp.x = __float2bfloat16(x); hp.y = __float2bfloat16(y);
    lp.x = __float2bfloat16(x - __bfloat162float(hp.x));
    lp.y = __float2bfloat16(y - __bfloat162float(hp.y));
    hi = *(uint32_t*)&hp; lo = *(uint32_t*)&lp;
}

__device__ __forceinline__ void ldm_x4(uint32_t& r0, uint32_t& r1, uint32_t& r2, uint32_t& r3,
                                       uint32_t addr) {
    asm volatile("ldmatrix.sync.aligned.m8n8.x4.shared.b16 {%0,%1,%2,%3}, [%4];\n"
                 : "=r"(r0), "=r"(r1), "=r"(r2), "=r"(r3) : "r"(addr));
}

__device__ __forceinline__ void ldm_x4_t(uint32_t& r0, uint32_t& r1, uint32_t& r2, uint32_t& r3,
                                         uint32_t addr) {
    asm volatile("ldmatrix.sync.aligned.m8n8.x4.trans.shared.b16 {%0,%1,%2,%3}, [%4];\n"
                 : "=r"(r0), "=r"(r1), "=r"(r2), "=r"(r3) : "r"(addr));
}

__device__ __forceinline__ void mma16816(float* d, const uint32_t* a, const uint32_t* b) {
    asm volatile(
        "mma.sync.aligned.m16n8k16.row.col.f32.bf16.bf16.f32 "
        "{%0,%1,%2,%3}, {%4,%5,%6,%7}, {%8,%9}, {%0,%1,%2,%3};\n"
        : "+f"(d[0]), "+f"(d[1]), "+f"(d[2]), "+f"(d[3])
        : "r"(a[0]), "r"(a[1]), "r"(a[2]), "r"(a[3]), "r"(b[0]), "r"(b[1]));
}

__device__ __forceinline__ void cp16(uint32_t dst, const void* src) {
    asm volatile("cp.async.cg.shared.global [%0], [%1], 16;\n" :: "r"(dst), "l"(src));
}

// ---------------------------------------------------------------------------
// Fused weight split
// ---------------------------------------------------------------------------
__global__ void wsplit_all(const float* s0, bf16* h0, bf16* l0, int n0,
                           const float* s1, bf16* h1, bf16* l1, int n1,
                           const float* s2, bf16* h2, bf16* l2, int n2,
                           const float* s3, bf16* h3, bf16* l3, int n3,
                           const float* s4, bf16* h4, bf16* l4, int n4) {
    const float* src; bf16* hi; bf16* lo; int n;
    switch (blockIdx.y) {
        case 0: src = s0; hi = h0; lo = l0; n = n0; break;
        case 1: src = s1; hi = h1; lo = l1; n = n1; break;
        case 2: src = s2; hi = h2; lo = l2; n = n2; break;
        case 3: src = s3; hi = h3; lo = l3; n = n3; break;
        default: src = s4; hi = h4; lo = l4; n = n4; break;
    }
    int i = (blockIdx.x * blockDim.x + threadIdx.x) * 4;
    if (i >= n) return;
    float4 v = *(const float4*)(src + i);
    uint32_t hh, ll;
    split2u(v.x, v.y, hh, ll);
    ((uint32_t*)(hi + i))[0] = hh; ((uint32_t*)(lo + i))[0] = ll;
    split2u(v.z, v.w, hh, ll);
    ((uint32_t*)(hi + i))[1] = hh; ((uint32_t*)(lo + i))[1] = ll;
}

// ---------------------------------------------------------------------------
// Embedding
// ---------------------------------------------------------------------------
__global__ void embed_kernel(const int* __restrict__ idx,
                             const float* __restrict__ wte,
                             const float* __restrict__ wpe,
                             float* __restrict__ x) {
    int token = blockIdx.x;
    int t = token % TT;
    int id = idx[token];
    const float4* src = (const float4*)(wte + (size_t)id * DD);
    const float4* pos = (const float4*)(wpe + (size_t)t * DD);
    float4* dst = (float4*)(x + (size_t)token * DD);
    for (int i = threadIdx.x; i < DD / 4; i += blockDim.x) {
        float4 a = src[i], b = pos[i];
        dst[i] = make_float4(a.x + b.x, a.y + b.y, a.z + b.z, a.w + b.w);
    }
}

// ---------------------------------------------------------------------------
// LayerNorm over D=1024 -> bf16 hi/lo
// ---------------------------------------------------------------------------
__global__ __launch_bounds__(256) void ln_split_kernel(const float* __restrict__ x,
                                                       const float* __restrict__ sc,
                                                       const float* __restrict__ bi,
                                                       bf16* __restrict__ ohi,
                                                       bf16* __restrict__ olo) {
    int token = blockIdx.x;
    const float4* xp = (const float4*)(x + (size_t)token * DD);
    float4 v = xp[threadIdx.x];
    float s = v.x + v.y + v.z + v.w;
    float q = v.x * v.x + v.y * v.y + v.z * v.z + v.w * v.w;
#pragma unroll
    for (int o = 16; o; o >>= 1) {
        s += __shfl_xor_sync(0xffffffffu, s, o);
        q += __shfl_xor_sync(0xffffffffu, q, o);
    }
    __shared__ float ss[8], sq[8];
    int w = threadIdx.x >> 5, l = threadIdx.x & 31;
    if (l == 0) { ss[w] = s; sq[w] = q; }
    __syncthreads();
    if (w == 0) {
        s = (l < 8) ? ss[l] : 0.f;
        q = (l < 8) ? sq[l] : 0.f;
#pragma unroll
        for (int o = 4; o; o >>= 1) {
            s += __shfl_xor_sync(0xffffffffu, s, o);
            q += __shfl_xor_sync(0xffffffffu, q, o);
        }
        if (l == 0) { ss[0] = s; sq[0] = q; }
    }
    __syncthreads();
    float mu  = ss[0] * (1.f / DD);
    float var = sq[0] * (1.f / DD) - mu * mu;
    float inv = rsqrtf(var + 1e-5f);
    float4 sv = ((const float4*)sc)[threadIdx.x];
    float4 bv = ((const float4*)bi)[threadIdx.x];
    float r0 = (v.x - mu) * inv * sv.x + bv.x;
    float r1 = (v.y - mu) * inv * sv.y + bv.y;
    float r2 = (v.z - mu) * inv * sv.z + bv.z;
    float r3 = (v.w - mu) * inv * sv.w + bv.w;
    size_t o = (size_t)token * DD + threadIdx.x * 4;
    uint32_t hh, ll;
    split2u(r0, r1, hh, ll);
    ((uint32_t*)(ohi + o))[0] = hh; ((uint32_t*)(olo + o))[0] = ll;
    split2u(r2, r3, hh, ll);
    ((uint32_t*)(ohi + o))[1] = hh; ((uint32_t*)(olo + o))[1] = ll;
}

// ---------------------------------------------------------------------------
// Tensor-core GEMM NT (R4 config): CTA 128x128, warp 64x32, BK=32, 3-pass.
// ---------------------------------------------------------------------------
#define FLAG_BIAS  1
#define FLAG_RES   2
#define FLAG_GELU  4
#define FLAG_SPLIT 8

__device__ __forceinline__ float gelu_exact(float v) {
    return 0.5f * v * (1.f + erff(v * 0.70710678118654752f));
}

__global__ __launch_bounds__(256) void gemm3(const bf16* __restrict__ Ah,
                                             const bf16* __restrict__ Al,
                                             const bf16* __restrict__ Bh,
                                             const bf16* __restrict__ Bl,
                                             const float* __restrict__ bias,
                                             const float* res,
                                             float* C, bf16* Chi, bf16* Clo,
                                             int M, int N, int K, int flags) {
    extern __shared__ __align__(16) bf16 sm[];
    int tid = threadIdx.x;
    int warp = tid >> 5, lane = tid & 31;
    int bm = blockIdx.y * BM, bn = blockIdx.x * BN;
    int wm = (warp >> 2) * 64;
    int wn = (warp & 3) * 32;

    uint32_t smbase = (uint32_t)__cvta_generic_to_shared(sm);

    float acc[4][4][4];
#pragma unroll
    for (int i = 0; i < 4; i++)
#pragma unroll
        for (int j = 0; j < 4; j++)
#pragma unroll
            for (int r = 0; r < 4; r++) acc[i][j][r] = 0.f;

    int a_r = ((lane >> 3) & 1) * 8 + (lane & 7);
    int a_c = (lane >> 4) * 8;
    int b_r = (lane >> 4) * 8 + (lane & 7);
    int b_c = ((lane >> 3) & 1) * 8;

    const bf16* srcs[4] = { Ah, Al, Bh, Bl };
    int rowbase[4] = { bm, bm, bn, bn };

    auto stage = [&](int buf, int k0) {
#pragma unroll
        for (int i = 0; i < 8; i++) {
            int arr = i >> 1;
            int c = tid + (i & 1) * 256;
            int row = c >> 2;
            int col = (c & 3) * 8;
            const bf16* src = srcs[arr] + (size_t)(rowbase[arr] + row) * K + k0 + col;
            uint32_t dst = smbase + (uint32_t)(buf * BUFSZ + arr * (BM * LDP) + row * LDP + col) * 2;
            cp16(dst, src);
        }
        asm volatile("cp.async.commit_group;\n");
    };

    stage(0, 0);
    int buf = 0;
    for (int k0 = 0; k0 < K; k0 += BK) {
        if (k0 + BK < K) {
            stage(buf ^ 1, k0 + BK);
            asm volatile("cp.async.wait_group 1;\n");
        } else {
            asm volatile("cp.async.wait_group 0;\n");
        }
        __syncthreads();

        uint32_t offAh = smbase + (uint32_t)(buf * BUFSZ) * 2;
        uint32_t offAl = offAh + (uint32_t)(BM * LDP) * 2;
        uint32_t offBh = offAl + (uint32_t)(BM * LDP) * 2;
        uint32_t offBl = offBh + (uint32_t)(BM * LDP) * 2;

#pragma unroll
        for (int ks = 0; ks < BK; ks += 16) {
            uint32_t ah[4][4], al[4][4], bh[4][2], bl[4][2];
#pragma unroll
            for (int mf = 0; mf < 4; mf++) {
                uint32_t addr = offAh + (uint32_t)((wm + mf * 16 + a_r) * LDP + ks + a_c) * 2;
                ldm_x4(ah[mf][0], ah[mf][1], ah[mf][2], ah[mf][3], addr);
            }
#pragma unroll
            for (int p = 0; p < 2; p++) {
                uint32_t addr = offBh + (uint32_t)((wn + p * 16 + b_r) * LDP + ks + b_c) * 2;
                uint32_t r0, r1, r2, r3;
                ldm_x4(r0, r1, r2, r3, addr);
                bh[2 * p][0] = r0; bh[2 * p][1] = r1;
                bh[2 * p + 1][0] = r2; bh[2 * p + 1][1] = r3;
            }
#pragma unroll
            for (int mf = 0; mf < 4; mf++)
#pragma unroll
                for (int nf = 0; nf < 4; nf++)
                    mma16816(acc[mf][nf], ah[mf], bh[nf]);

#pragma unroll
            for (int p = 0; p < 2; p++) {
                uint32_t addr = offBl + (uint32_t)((wn + p * 16 + b_r) * LDP + ks + b_c) * 2;
                uint32_t r0, r1, r2, r3;
                ldm_x4(r0, r1, r2, r3, addr);
                bl[2 * p][0] = r0; bl[2 * p][1] = r1;
                bl[2 * p + 1][0] = r2; bl[2 * p + 1][1] = r3;
            }
#pragma unroll
            for (int mf = 0; mf < 4; mf++)
#pragma unroll
                for (int nf = 0; nf < 4; nf++)
                    mma16816(acc[mf][nf], ah[mf], bl[nf]);

#pragma unroll
            for (int mf = 0; mf < 4; mf++) {
                uint32_t addr = offAl + (uint32_t)((wm + mf * 16 + a_r) * LDP + ks + a_c) * 2;
                ldm_x4(al[mf][0], al[mf][1], al[mf][2], al[mf][3], addr);
            }
#pragma unroll
            for (int mf = 0; mf < 4; mf++)
#pragma unroll
                for (int nf = 0; nf < 4; nf++)
                    mma16816(acc[mf][nf], al[mf], bh[nf]);
        }
        __syncthreads();
        buf ^= 1;
    }

    int gid = lane >> 2, tg = lane & 3;
#pragma unroll
    for (int mf = 0; mf < 4; mf++) {
#pragma unroll
        for (int half = 0; half < 2; half++) {
            int row = bm + wm + mf * 16 + half * 8 + gid;
#pragma unroll
            for (int nf = 0; nf < 4; nf++) {
                int col = bn + wn + nf * 8 + tg * 2;
                float2 o;
                o.x = acc[mf][nf][half * 2 + 0];
                o.y = acc[mf][nf][half * 2 + 1];
                if (flags & FLAG_BIAS) { o.x += bias[col]; o.y += bias[col + 1]; }
                if (flags & FLAG_GELU) { o.x = gelu_exact(o.x); o.y = gelu_exact(o.y); }
                if (flags & FLAG_RES) {
                    float2 r = *(const float2*)(res + (size_t)row * N + col);
                    o.x += r.x; o.y += r.y;
                }
                if (flags & FLAG_SPLIT) {
                    size_t off = (size_t)row * N + col;
                    uint32_t hh, ll;
                    split2u(o.x, o.y, hh, ll);
                    *(uint32_t*)(Chi + off) = hh;
                    *(uint32_t*)(Clo + off) = ll;
                } else {
                    *(float2*)(C + (size_t)row * N + col) = o;
                }
            }
        }
    }
}

// ---------------------------------------------------------------------------
// Causal attention via mma.sync (flash-attention, bf16-split fp32-accurate).
// Block: 128 queries (8 warps x 16). Key tiles of 64. One (b,h) per block.z/y.
// ---------------------------------------------------------------------------
__global__ __launch_bounds__(256) void attn_mma(const float* __restrict__ qkv,
                                                bf16* __restrict__ yhi,
                                                bf16* __restrict__ ylo) {
    int b = blockIdx.z, h = blockIdx.y;
    int bx = gridDim.x - 1 - blockIdx.x;   // heavy blocks scheduled first
    int tid = threadIdx.x;
    int warp = tid >> 5, lane = tid & 31;
    int g = lane >> 2, t4 = lane & 3;
    int q0w = bx * AQ + warp * 16;

    __shared__ __align__(16) bf16 Kh_s[AKT * LDV];
    __shared__ __align__(16) bf16 Kl_s[AKT * LDV];
    __shared__ __align__(16) bf16 Vh_s[AKT * LDV];
    __shared__ __align__(16) bf16 Vl_s[AKT * LDV];
    uint32_t aKh = (uint32_t)__cvta_generic_to_shared(Kh_s);
    uint32_t aKl = (uint32_t)__cvta_generic_to_shared(Kl_s);
    uint32_t aVh = (uint32_t)__cvta_generic_to_shared(Vh_s);
    uint32_t aVl = (uint32_t)__cvta_generic_to_shared(Vl_s);

    // Q a-frags (scaled by 1/8), hi/lo: 4 k-chunks x 4 regs
    uint32_t qh[4][4], ql[4][4];
    {
        const float* qbase = qkv + (size_t)(b * TT) * (3 * DD) + h * HDIM;
        const float* r0p = qbase + (size_t)(q0w + g) * (3 * DD);
        const float* r1p = qbase + (size_t)(q0w + g + 8) * (3 * DD);
#pragma unroll
        for (int c = 0; c < 4; c++) {
            float2 v00 = *(const float2*)(r0p + c * 16 + 2 * t4);
            float2 v10 = *(const float2*)(r1p + c * 16 + 2 * t4);
            float2 v01 = *(const float2*)(r0p + c * 16 + 2 * t4 + 8);
            float2 v11 = *(const float2*)(r1p + c * 16 + 2 * t4 + 8);
            split2u(v00.x * 0.125f, v00.y * 0.125f, qh[c][0], ql[c][0]);
            split2u(v10.x * 0.125f, v10.y * 0.125f, qh[c][1], ql[c][1]);
            split2u(v01.x * 0.125f, v01.y * 0.125f, qh[c][2], ql[c][2]);
            split2u(v11.x * 0.125f, v11.y * 0.125f, qh[c][3], ql[c][3]);
        }
    }

    float O[8][4];
#pragma unroll
    for (int j = 0; j < 8; j++)
#pragma unroll
        for (int r = 0; r < 4; r++) O[j][r] = 0.f;
    float m0 = NEGINF, m1 = NEGINF, l0 = 0.f, l1 = 0.f;

    // ldmatrix lane addressing
    int b_r = (lane >> 4) * 8 + (lane & 7);        // K frags: key row / dim col split
    int b_c = ((lane >> 3) & 1) * 8;
    int v_r = (lane & 7) + ((lane >> 3) & 1) * 8;  // V trans frags
    int v_c = (lane >> 4) * 8;

    const float* kb = qkv + (size_t)(b * TT) * (3 * DD) + DD + h * HDIM;
    const float* vb = kb + DD;

    int ntiles = bx * 2 + 2;
    for (int tile = 0; tile < ntiles; tile++) {
        int kt = tile * AKT;
        __syncthreads();
        // stage K,V tile: 64 keys x 64 dims, fp32 -> bf16 hi/lo
#pragma unroll
        for (int i = 0; i < 8; i++) {
            int cid = tid + i * 256;             // 0..2047
            int kk = cid >> 5;
            int d2 = (cid & 31) * 2;
            const float* kr = kb + (size_t)(kt + kk) * (3 * DD) + d2;
            const float* vr = vb + (size_t)(kt + kk) * (3 * DD) + d2;
            float2 kv = *(const float2*)kr;
            float2 vv = *(const float2*)vr;
            uint32_t hh, ll;
            split2u(kv.x, kv.y, hh, ll);
            *(uint32_t*)(Kh_s + kk * LDV + d2) = hh;
            *(uint32_t*)(Kl_s + kk * LDV + d2) = ll;
            split2u(vv.x, vv.y, hh, ll);
            *(uint32_t*)(Vh_s + kk * LDV + d2) = hh;
            *(uint32_t*)(Vl_s + kk * LDV + d2) = ll;
        }
        __syncthreads();

        if (kt > q0w + 15) continue;

        // ----- S = Q K^T (3-pass split) -----
        float S[8][4];
#pragma unroll
        for (int j = 0; j < 8; j++)
#pragma unroll
            for (int r = 0; r < 4; r++) S[j][r] = 0.f;

#pragma unroll
        for (int c = 0; c < 4; c++) {            // dim chunk (k)
            uint32_t kf[8][2];
#pragma unroll
            for (int p = 0; p < 4; p++) {        // key strip of 16
                uint32_t r0, r1, r2, r3;
                ldm_x4(r0, r1, r2, r3, aKh + (uint32_t)((16 * p + b_r) * LDV + 16 * c + b_c) * 2);
                kf[2 * p][0] = r0; kf[2 * p][1] = r1;
                kf[2 * p + 1][0] = r2; kf[2 * p + 1][1] = r3;
            }
#pragma unroll
            for (int j = 0; j < 8; j++) mma16816(S[j], qh[c], kf[j]);
#pragma unroll
            for (int j = 0; j < 8; j++) mma16816(S[j], ql[c], kf[j]);
#pragma unroll
            for (int p = 0; p < 4; p++) {
                uint32_t r0, r1, r2, r3;
                ldm_x4(r0, r1, r2, r3, aKl + (uint32_t)((16 * p + b_r) * LDV + 16 * c + b_c) * 2);
                kf[2 * p][0] = r0; kf[2 * p][1] = r1;
                kf[2 * p + 1][0] = r2; kf[2 * p + 1][1] = r3;
            }
#pragma unroll
            for (int j = 0; j < 8; j++) mma16816(S[j], qh[c], kf[j]);
        }

        // ----- causal mask (only needed on boundary tiles) -----
        if (kt + AKT - 1 > q0w) {
            int row0 = q0w + g, row1 = q0w + g + 8;
#pragma unroll
            for (int j = 0; j < 8; j++) {
                int col = kt + 8 * j + 2 * t4;
                if (col > row0)     S[j][0] = NEGINF;
                if (col + 1 > row0) S[j][1] = NEGINF;
                if (col > row1)     S[j][2] = NEGINF;
                if (col + 1 > row1) S[j][3] = NEGINF;
            }
        }

        // ----- online softmax -----
        float mx0 = NEGINF, mx1 = NEGINF;
#pragma unroll
        for (int j = 0; j < 8; j++) {
            mx0 = fmaxf(mx0, fmaxf(S[j][0], S[j][1]));
            mx1 = fmaxf(mx1, fmaxf(S[j][2], S[j][3]));
        }
        mx0 = fmaxf(mx0, __shfl_xor_sync(0xffffffffu, mx0, 1));
        mx0 = fmaxf(mx0, __shfl_xor_sync(0xffffffffu, mx0, 2));
        mx1 = fmaxf(mx1, __shfl_xor_sync(0xffffffffu, mx1, 1));
        mx1 = fmaxf(mx1, __shfl_xor_sync(0xffffffffu, mx1, 2));
        float m0n = fmaxf(m0, mx0), m1n = fmaxf(m1, mx1);
        float c0 = __expf(m0 - m0n), c1 = __expf(m1 - m1n);
        float s0 = 0.f, s1 = 0.f;
#pragma unroll
        for (int j = 0; j < 8; j++) {
            S[j][0] = __expf(S[j][0] - m0n);
            S[j][1] = __expf(S[j][1] - m0n);
            S[j][2] = __expf(S[j][2] - m1n);
            S[j][3] = __expf(S[j][3] - m1n);
            s0 += S[j][0] + S[j][1];
            s1 += S[j][2] + S[j][3];
        }
        s0 += __shfl_xor_sync(0xffffffffu, s0, 1);
        s0 += __shfl_xor_sync(0xffffffffu, s0, 2);
        s1 += __shfl_xor_sync(0xffffffffu, s1, 1);
        s1 += __shfl_xor_sync(0xffffffffu, s1, 2);
        l0 = l0 * c0 + s0;
        l1 = l1 * c1 + s1;
        m0 = m0n; m1 = m1n;
#pragma unroll
        for (int j = 0; j < 8; j++) {
            O[j][0] *= c0; O[j][1] *= c0;
            O[j][2] *= c1; O[j][3] *= c1;
        }

        // ----- O += P V (3-pass split) -----
#pragma unroll
        for (int kk = 0; kk < 4; kk++) {         // key chunk of 16
            uint32_t ph[4], pl[4];
            split2u(S[2 * kk][0],     S[2 * kk][1],     ph[0], pl[0]);
            split2u(S[2 * kk][2],     S[2 * kk][3],     ph[1], pl[1]);
            split2u(S[2 * kk + 1][0], S[2 * kk + 1][1], ph[2], pl[2]);
            split2u(S[2 * kk + 1][2], S[2 * kk + 1][3], ph[3], pl[3]);

            uint32_t vf[8][2];
#pragma unroll
            for (int ds = 0; ds < 4; ds++) {     // dim strip of 16
                uint32_t r0, r1, r2, r3;
                ldm_x4_t(r0, r1, r2, r3, aVh + (uint32_t)((16 * kk + v_r) * LDV + 16 * ds + v_c) * 2);
                vf[2 * ds][0] = r0; vf[2 * ds][1] = r1;
                vf[2 * ds + 1][0] = r2; vf[2 * ds + 1][1] = r3;
            }
#pragma unroll
            for (int j = 0; j < 8; j++) mma16816(O[j], ph, vf[j]);
#pragma unroll
            for (int j = 0; j < 8; j++) mma16816(O[j], pl, vf[j]);
#pragma unroll
            for (int ds = 0; ds < 4; ds++) {
                uint32_t r0, r1, r2, r3;
                ldm_x4_t(r0, r1, r2, r3, aVl + (uint32_t)((16 * kk + v_r) * LDV + 16 * ds + v_c) * 2);
                vf[2 * ds][0] = r0; vf[2 * ds][1] = r1;
                vf[2 * ds + 1][0] = r2; vf[2 * ds + 1][1] = r3;
            }
#pragma unroll
            for (int j = 0; j < 8; j++) mma16816(O[j], ph, vf[j]);
        }
    }

    // epilogue: normalize and store y hi/lo
    float i0 = 1.f / l0, i1 = 1.f / l1;
    size_t off0 = (size_t)(b * TT + q0w + g) * DD + h * HDIM + 2 * t4;
    size_t off1 = (size_t)(b * TT + q0w + g + 8) * DD + h * HDIM + 2 * t4;
#pragma unroll
    for (int j = 0; j < 8; j++) {
        uint32_t hh, ll;
        split2u(O[j][0] * i0, O[j][1] * i0, hh, ll);
        *(uint32_t*)(yhi + off0 + 8 * j) = hh;
        *(uint32_t*)(ylo + off0 + 8 * j) = ll;
        split2u(O[j][2] * i1, O[j][3] * i1, hh, ll);
        *(uint32_t*)(yhi + off1 + 8 * j) = hh;
        *(uint32_t*)(ylo + off1 + 8 * j) = ll;
    }
}

// ---------------------------------------------------------------------------
// Host launcher
// ---------------------------------------------------------------------------
extern "C" void kernel_launch(void* const* d_in, const int* in_sizes, int n_in,
                              void* d_out, int out_size) {
    const int*   idx    = (const int*)  d_in[0];
    const float* wte    = (const float*)d_in[1];
    const float* wpe    = (const float*)d_in[2];
    const float* ln1_s  = (const float*)d_in[3];
    const float* ln1_b  = (const float*)d_in[4];
    const float* qkv_w  = (const float*)d_in[5];
    const float* proj_w = (const float*)d_in[6];
    const float* ln2_s  = (const float*)d_in[7];
    const float* ln2_b  = (const float*)d_in[8];
    const float* fc_w   = (const float*)d_in[9];
    const float* fc_b   = (const float*)d_in[10];
    const float* fc2_w  = (const float*)d_in[11];
    const float* fc2_b  = (const float*)d_in[12];
    const float* lnf_s  = (const float*)d_in[13];
    const float* lnf_b  = (const float*)d_in[14];
    const float* lm_w   = (const float*)d_in[15];
    float* out = (float*)d_out;

    float *x, *qkv;
    bf16 *h_hi, *h_lo, *y_hi, *y_lo, *gg_hi, *gg_lo;
    bf16 *qw_hi, *qw_lo, *pw_hi, *pw_lo, *fw_hi, *fw_lo, *f2_hi, *f2_lo, *lw_hi, *lw_lo;
    cudaGetSymbolAddress((void**)&x,     g_x);
    cudaGetSymbolAddress((void**)&qkv,   g_qkv);
    cudaGetSymbolAddress((void**)&h_hi,  g_h_hi);   cudaGetSymbolAddress((void**)&h_lo,  g_h_lo);
    cudaGetSymbolAddress((void**)&y_hi,  g_y_hi);   cudaGetSymbolAddress((void**)&y_lo,  g_y_lo);
    cudaGetSymbolAddress((void**)&gg_hi, g_g_hi);   cudaGetSymbolAddress((void**)&gg_lo, g_g_lo);
    cudaGetSymbolAddress((void**)&qw_hi, g_qkvw_hi); cudaGetSymbolAddress((void**)&qw_lo, g_qkvw_lo);
    cudaGetSymbolAddress((void**)&pw_hi, g_projw_hi); cudaGetSymbolAddress((void**)&pw_lo, g_projw_lo);
    cudaGetSymbolAddress((void**)&fw_hi, g_fcw_hi);  cudaGetSymbolAddress((void**)&fw_lo, g_fcw_lo);
    cudaGetSymbolAddress((void**)&f2_hi, g_fc2w_hi); cudaGetSymbolAddress((void**)&f2_lo, g_fc2w_lo);
    cudaGetSymbolAddress((void**)&lw_hi, g_lmw_hi);  cudaGetSymbolAddress((void**)&lw_lo, g_lmw_lo);

    cudaFuncSetAttribute(gemm3, cudaFuncAttributeMaxDynamicSharedMemorySize, GSM);

    embed_kernel<<<MM, 256>>>(idx, wte, wpe, x);

    {
        int nq = LL * 3 * DD * DD, np = LL * DD * DD;
        int nf = LL * 4 * DD * DD, n2 = LL * 4 * DD * DD, nl = VV * DD;
        int maxn = nf;
        dim3 grid((maxn / 4 + 255) / 256, 5);
        wsplit_all<<<grid, 256>>>(qkv_w,  qw_hi, qw_lo, nq,
                                  proj_w, pw_hi, pw_lo, np,
                                  fc_w,   fw_hi, fw_lo, nf,
                                  fc2_w,  f2_hi, f2_lo, n2,
                                  lm_w,   lw_hi, lw_lo, nl);
    }

    for (int l = 0; l < LL; l++) {
        bf16* qwh = qw_hi + (size_t)l * 3 * DD * DD;  bf16* qwl = qw_lo + (size_t)l * 3 * DD * DD;
        bf16* pwh = pw_hi + (size_t)l * DD * DD;      bf16* pwl = pw_lo + (size_t)l * DD * DD;
        bf16* fwh = fw_hi + (size_t)l * 4 * DD * DD;  bf16* fwl = fw_lo + (size_t)l * 4 * DD * DD;
        bf16* f2h = f2_hi + (size_t)l * 4 * DD * DD;  bf16* f2l = f2_lo + (size_t)l * 4 * DD * DD;
        const float* fb  = fc_b  + (size_t)l * 4 * DD;
        const float* f2b = fc2_b + (size_t)l * DD;

        ln_split_kernel<<<MM, 256>>>(x, ln1_s + l * DD, ln1_b + l * DD, h_hi, h_lo);
        gemm3<<<dim3(3 * DD / BN, MM / BM), 256, GSM>>>(h_hi, h_lo, qwh, qwl,
            nullptr, nullptr, qkv, nullptr, nullptr, MM, 3 * DD, DD, 0);
        attn_mma<<<dim3(TT / AQ, HH, BB), 256>>>(qkv, y_hi, y_lo);
        gemm3<<<dim3(DD / BN, MM / BM), 256, GSM>>>(y_hi, y_lo, pwh, pwl,
            nullptr, x, x, nullptr, nullptr, MM, DD, DD, FLAG_RES);
        ln_split_kernel<<<MM, 256>>>(x, ln2_s + l * DD, ln2_b + l * DD, h_hi, h_lo);
        gemm3<<<dim3(4 * DD / BN, MM / BM), 256, GSM>>>(h_hi, h_lo, fwh, fwl,
            fb, nullptr, nullptr, gg_hi, gg_lo, MM, 4 * DD, DD, FLAG_BIAS | FLAG_GELU | FLAG_SPLIT);
        gemm3<<<dim3(DD / BN, MM / BM), 256, GSM>>>(gg_hi, gg_lo, f2h, f2l,
            f2b, x, x, nullptr, nullptr, MM, DD, 4 * DD, FLAG_BIAS | FLAG_RES);
    }

    ln_split_kernel<<<MM, 256>>>(x, lnf_s, lnf_b, h_hi, h_lo);
    gemm3<<<dim3(VV / BN, MM / BM), 256, GSM>>>(h_hi, h_lo, lw_hi, lw_lo,
        nullptr, nullptr, out, nullptr, nullptr, MM, VV, DD, 0);
}

// round 8
// speedup vs baseline: 1.7070x; 1.0991x over previous
#include <cuda_runtime.h>
#include <cuda_bf16.h>
#include <math.h>
#include <stdint.h>

// Model dims
#define BB   2
#define TT   1024
#define DD   1024
#define HH   16
#define HDIM 64
#define LL   8
#define VV   32000
#define MM   (BB*TT)   // 2048 tokens

typedef __nv_bfloat16 bf16;
typedef __nv_bfloat162 bf162;

// GEMM tiling: CTA 128x128, warp 64x32, BK=32, 3-stage swizzled pipeline
#define BM 128
#define BN 128
#define BK 32
#define TILEB 8192            // 128 rows x 64 bytes (32 bf16), packed + swizzled
#define BUFB (4*TILEB)        // Ah, Al, Bh, Bl = 32768 bytes
#define NSTAGE 3
#define GSM (NSTAGE * BUFB)   // 98304 bytes

// Attention tiling
#define AQ  128
#define AKT 64
#define LDV 72
#define NEGINF (-1e30f)

// fp32 scratch
__device__ float g_x  [MM * DD];
__device__ float g_qkv[MM * 3 * DD];
// bf16 hi/lo activation scratch
__device__ bf16 g_h_hi[MM * DD],     g_h_lo[MM * DD];
__device__ bf16 g_y_hi[MM * DD],     g_y_lo[MM * DD];
__device__ bf16 g_g_hi[MM * 4 * DD], g_g_lo[MM * 4 * DD];
// bf16 hi/lo weight scratch
__device__ bf16 g_qkvw_hi[LL * 3 * DD * DD], g_qkvw_lo[LL * 3 * DD * DD];
__device__ bf16 g_projw_hi[LL * DD * DD],    g_projw_lo[LL * DD * DD];
__device__ bf16 g_fcw_hi [LL * 4 * DD * DD], g_fcw_lo [LL * 4 * DD * DD];
__device__ bf16 g_fc2w_hi[LL * 4 * DD * DD], g_fc2w_lo[LL * 4 * DD * DD];
__device__ bf16 g_lmw_hi [VV * DD],          g_lmw_lo [VV * DD];

// ---------------------------------------------------------------------------
// Small helpers
// ---------------------------------------------------------------------------
__device__ __forceinline__ void split2u(float x, float y, uint32_t& hi, uint32_t& lo) {
    bf162 hp, lp;
    hp.x = __float2bfloat16(x); hp.y = __float2bfloat16(y);
    lp.x = __float2bfloat16(x - __bfloat162float(hp.x));
    lp.y = __float2bfloat16(y - __bfloat162float(hp.y));
    hi = *(uint32_t*)&hp; lo = *(uint32_t*)&lp;
}

__device__ __forceinline__ void ldm_x4(uint32_t& r0, uint32_t& r1, uint32_t& r2, uint32_t& r3,
                                       uint32_t addr) {
    asm volatile("ldmatrix.sync.aligned.m8n8.x4.shared.b16 {%0,%1,%2,%3}, [%4];\n"
                 : "=r"(r0), "=r"(r1), "=r"(r2), "=r"(r3) : "r"(addr));
}

__device__ __forceinline__ void ldm_x4_t(uint32_t& r0, uint32_t& r1, uint32_t& r2, uint32_t& r3,
                                         uint32_t addr) {
    asm volatile("ldmatrix.sync.aligned.m8n8.x4.trans.shared.b16 {%0,%1,%2,%3}, [%4];\n"
                 : "=r"(r0), "=r"(r1), "=r"(r2), "=r"(r3) : "r"(addr));
}

__device__ __forceinline__ void mma16816(float* d, const uint32_t* a, const uint32_t* b) {
    asm volatile(
        "mma.sync.aligned.m16n8k16.row.col.f32.bf16.bf16.f32 "
        "{%0,%1,%2,%3}, {%4,%5,%6,%7}, {%8,%9}, {%0,%1,%2,%3};\n"
        : "+f"(d[0]), "+f"(d[1]), "+f"(d[2]), "+f"(d[3])
        : "r"(a[0]), "r"(a[1]), "r"(a[2]), "r"(a[3]), "r"(b[0]), "r"(b[1]));
}

__device__ __forceinline__ void cp16(uint32_t dst, const void* src) {
    asm volatile("cp.async.cg.shared.global [%0], [%1], 16;\n" :: "r"(dst), "l"(src));
}

// swizzled byte offset within one 128x32(bf16) tile: row r, 16B chunk c (0..3)
__device__ __forceinline__ uint32_t swz(int r, int c) {
    return (uint32_t)(r * 64 + ((c ^ ((r >> 1) & 3)) << 4));
}

// ---------------------------------------------------------------------------
// Fused weight split
// ---------------------------------------------------------------------------
__global__ void wsplit_all(const float* s0, bf16* h0, bf16* l0, int n0,
                           const float* s1, bf16* h1, bf16* l1, int n1,
                           const float* s2, bf16* h2, bf16* l2, int n2,
                           const float* s3, bf16* h3, bf16* l3, int n3,
                           const float* s4, bf16* h4, bf16* l4, int n4) {
    const float* src; bf16* hi; bf16* lo; int n;
    switch (blockIdx.y) {
        case 0: src = s0; hi = h0; lo = l0; n = n0; break;
        case 1: src = s1; hi = h1; lo = l1; n = n1; break;
        case 2: src = s2; hi = h2; lo = l2; n = n2; break;
        case 3: src = s3; hi = h3; lo = l3; n = n3; break;
        default: src = s4; hi = h4; lo = l4; n = n4; break;
    }
    int i = (blockIdx.x * blockDim.x + threadIdx.x) * 4;
    if (i >= n) return;
    float4 v = *(const float4*)(src + i);
    uint32_t hh, ll;
    split2u(v.x, v.y, hh, ll);
    ((uint32_t*)(hi + i))[0] = hh; ((uint32_t*)(lo + i))[0] = ll;
    split2u(v.z, v.w, hh, ll);
    ((uint32_t*)(hi + i))[1] = hh; ((uint32_t*)(lo + i))[1] = ll;
}

// ---------------------------------------------------------------------------
// Embedding
// ---------------------------------------------------------------------------
__global__ void embed_kernel(const int* __restrict__ idx,
                             const float* __restrict__ wte,
                             const float* __restrict__ wpe,
                             float* __restrict__ x) {
    int token = blockIdx.x;
    int t = token % TT;
    int id = idx[token];
    const float4* src = (const float4*)(wte + (size_t)id * DD);
    const float4* pos = (const float4*)(wpe + (size_t)t * DD);
    float4* dst = (float4*)(x + (size_t)token * DD);
    for (int i = threadIdx.x; i < DD / 4; i += blockDim.x) {
        float4 a = src[i], b = pos[i];
        dst[i] = make_float4(a.x + b.x, a.y + b.y, a.z + b.z, a.w + b.w);
    }
}

// ---------------------------------------------------------------------------
// LayerNorm over D=1024 -> bf16 hi/lo
// ---------------------------------------------------------------------------
__global__ __launch_bounds__(256) void ln_split_kernel(const float* __restrict__ x,
                                                       const float* __restrict__ sc,
                                                       const float* __restrict__ bi,
                                                       bf16* __restrict__ ohi,
                                                       bf16* __restrict__ olo) {
    int token = blockIdx.x;
    const float4* xp = (const float4*)(x + (size_t)token * DD);
    float4 v = xp[threadIdx.x];
    float s = v.x + v.y + v.z + v.w;
    float q = v.x * v.x + v.y * v.y + v.z * v.z + v.w * v.w;
#pragma unroll
    for (int o = 16; o; o >>= 1) {
        s += __shfl_xor_sync(0xffffffffu, s, o);
        q += __shfl_xor_sync(0xffffffffu, q, o);
    }
    __shared__ float ss[8], sq[8];
    int w = threadIdx.x >> 5, l = threadIdx.x & 31;
    if (l == 0) { ss[w] = s; sq[w] = q; }
    __syncthreads();
    if (w == 0) {
        s = (l < 8) ? ss[l] : 0.f;
        q = (l < 8) ? sq[l] : 0.f;
#pragma unroll
        for (int o = 4; o; o >>= 1) {
            s += __shfl_xor_sync(0xffffffffu, s, o);
            q += __shfl_xor_sync(0xffffffffu, q, o);
        }
        if (l == 0) { ss[0] = s; sq[0] = q; }
    }
    __syncthreads();
    float mu  = ss[0] * (1.f / DD);
    float var = sq[0] * (1.f / DD) - mu * mu;
    float inv = rsqrtf(var + 1e-5f);
    float4 sv = ((const float4*)sc)[threadIdx.x];
    float4 bv = ((const float4*)bi)[threadIdx.x];
    float r0 = (v.x - mu) * inv * sv.x + bv.x;
    float r1 = (v.y - mu) * inv * sv.y + bv.y;
    float r2 = (v.z - mu) * inv * sv.z + bv.z;
    float r3 = (v.w - mu) * inv * sv.w + bv.w;
    size_t o = (size_t)token * DD + threadIdx.x * 4;
    uint32_t hh, ll;
    split2u(r0, r1, hh, ll);
    ((uint32_t*)(ohi + o))[0] = hh; ((uint32_t*)(olo + o))[0] = ll;
    split2u(r2, r3, hh, ll);
    ((uint32_t*)(ohi + o))[1] = hh; ((uint32_t*)(olo + o))[1] = ll;
}

// ---------------------------------------------------------------------------
// Tensor-core GEMM NT: CTA 128x128, warp 64x32, BK=32, 3-pass bf16-split.
// 3-stage cp.async pipeline, swizzled smem, ONE __syncthreads per stage.
// ---------------------------------------------------------------------------
#define FLAG_BIAS  1
#define FLAG_RES   2
#define FLAG_GELU  4
#define FLAG_SPLIT 8

__device__ __forceinline__ float gelu_exact(float v) {
    return 0.5f * v * (1.f + erff(v * 0.70710678118654752f));
}

__global__ __launch_bounds__(256) void gemm3(const bf16* __restrict__ Ah,
                                             const bf16* __restrict__ Al,
                                             const bf16* __restrict__ Bh,
                                             const bf16* __restrict__ Bl,
                                             const float* __restrict__ bias,
                                             const float* res,
                                             float* C, bf16* Chi, bf16* Clo,
                                             int M, int N, int K, int flags) {
    extern __shared__ __align__(16) bf16 sm[];
    int tid = threadIdx.x;
    int warp = tid >> 5, lane = tid & 31;
    int bm = blockIdx.y * BM, bn = blockIdx.x * BN;
    int wm = (warp >> 2) * 64;
    int wn = (warp & 3) * 32;

    uint32_t smbase = (uint32_t)__cvta_generic_to_shared(sm);

    float acc[4][4][4];
#pragma unroll
    for (int i = 0; i < 4; i++)
#pragma unroll
        for (int j = 0; j < 4; j++)
#pragma unroll
            for (int r = 0; r < 4; r++) acc[i][j][r] = 0.f;

    int a_r = ((lane >> 3) & 1) * 8 + (lane & 7);
    int a_c = (lane >> 4) * 8;
    int b_r = (lane >> 4) * 8 + (lane & 7);
    int b_c = ((lane >> 3) & 1) * 8;

    const bf16* srcs[4] = { Ah, Al, Bh, Bl };
    int rowbase[4] = { bm, bm, bn, bn };

    // one stage = 4 tiles x 128 rows x 4 chunks(16B) = 2048 cp.async of 16B
    auto stage = [&](int s_idx, int buf) {
        int k0 = s_idx * BK;
        uint32_t bufoff = smbase + (uint32_t)(buf * BUFB);
#pragma unroll
        for (int i = 0; i < 8; i++) {
            int cid = tid + i * 256;       // 0..2047
            int arr = cid >> 9;            // 512 chunks per tile
            int sub = cid & 511;
            int row = sub >> 2;
            int c = sub & 3;
            const bf16* src = srcs[arr] + (size_t)(rowbase[arr] + row) * K + k0 + c * 8;
            cp16(bufoff + (uint32_t)(arr * TILEB) + swz(row, c), src);
        }
        asm volatile("cp.async.commit_group;\n");
    };

    int S = K / BK;
    stage(0, 0);
    stage(1, 1);

    for (int s = 0; s < S; s++) {
        int buf = s - (s / NSTAGE) * NSTAGE;   // s % 3
        if (s == S - 1) asm volatile("cp.async.wait_group 0;\n");
        else            asm volatile("cp.async.wait_group 1;\n");
        __syncthreads();
        if (s + 2 < S) stage(s + 2, (s + 2) % NSTAGE);

        uint32_t offAh = smbase + (uint32_t)(buf * BUFB);
        uint32_t offAl = offAh + TILEB;
        uint32_t offBh = offAl + TILEB;
        uint32_t offBl = offBh + TILEB;

#pragma unroll
        for (int ks = 0; ks < BK; ks += 16) {
            uint32_t ah[4][4], al[4][4], bh[4][2], bl[4][2];
#pragma unroll
            for (int mf = 0; mf < 4; mf++) {
                int row = wm + mf * 16 + a_r;
                ldm_x4(ah[mf][0], ah[mf][1], ah[mf][2], ah[mf][3],
                       offAh + swz(row, (ks + a_c) >> 3));
            }
#pragma unroll
            for (int p = 0; p < 2; p++) {
                int row = wn + p * 16 + b_r;
                uint32_t r0, r1, r2, r3;
                ldm_x4(r0, r1, r2, r3, offBh + swz(row, (ks + b_c) >> 3));
                bh[2 * p][0] = r0; bh[2 * p][1] = r1;
                bh[2 * p + 1][0] = r2; bh[2 * p + 1][1] = r3;
            }
#pragma unroll
            for (int mf = 0; mf < 4; mf++)
#pragma unroll
                for (int nf = 0; nf < 4; nf++)
                    mma16816(acc[mf][nf], ah[mf], bh[nf]);

#pragma unroll
            for (int p = 0; p < 2; p++) {
                int row = wn + p * 16 + b_r;
                uint32_t r0, r1, r2, r3;
                ldm_x4(r0, r1, r2, r3, offBl + swz(row, (ks + b_c) >> 3));
                bl[2 * p][0] = r0; bl[2 * p][1] = r1;
                bl[2 * p + 1][0] = r2; bl[2 * p + 1][1] = r3;
            }
#pragma unroll
            for (int mf = 0; mf < 4; mf++)
#pragma unroll
                for (int nf = 0; nf < 4; nf++)
                    mma16816(acc[mf][nf], ah[mf], bl[nf]);

#pragma unroll
            for (int mf = 0; mf < 4; mf++) {
                int row = wm + mf * 16 + a_r;
                ldm_x4(al[mf][0], al[mf][1], al[mf][2], al[mf][3],
                       offAl + swz(row, (ks + a_c) >> 3));
            }
#pragma unroll
            for (int mf = 0; mf < 4; mf++)
#pragma unroll
                for (int nf = 0; nf < 4; nf++)
                    mma16816(acc[mf][nf], al[mf], bh[nf]);
        }
    }

    int gid = lane >> 2, tg = lane & 3;
#pragma unroll
    for (int mf = 0; mf < 4; mf++) {
#pragma unroll
        for (int half = 0; half < 2; half++) {
            int row = bm + wm + mf * 16 + half * 8 + gid;
#pragma unroll
            for (int nf = 0; nf < 4; nf++) {
                int col = bn + wn + nf * 8 + tg * 2;
                float2 o;
                o.x = acc[mf][nf][half * 2 + 0];
                o.y = acc[mf][nf][half * 2 + 1];
                if (flags & FLAG_BIAS) { o.x += bias[col]; o.y += bias[col + 1]; }
                if (flags & FLAG_GELU) { o.x = gelu_exact(o.x); o.y = gelu_exact(o.y); }
                if (flags & FLAG_RES) {
                    float2 r = *(const float2*)(res + (size_t)row * N + col);
                    o.x += r.x; o.y += r.y;
                }
                if (flags & FLAG_SPLIT) {
                    size_t off = (size_t)row * N + col;
                    uint32_t hh, ll;
                    split2u(o.x, o.y, hh, ll);
                    *(uint32_t*)(Chi + off) = hh;
                    *(uint32_t*)(Clo + off) = ll;
                } else {
                    *(float2*)(C + (size_t)row * N + col) = o;
                }
            }
        }
    }
}

// ---------------------------------------------------------------------------
// Causal attention via mma.sync (flash-attention, bf16-split fp32-accurate).
// ---------------------------------------------------------------------------
__global__ __launch_bounds__(256) void attn_mma(const float* __restrict__ qkv,
                                                bf16* __restrict__ yhi,
                                                bf16* __restrict__ ylo) {
    int b = blockIdx.z, h = blockIdx.y;
    int bx = gridDim.x - 1 - blockIdx.x;
    int tid = threadIdx.x;
    int warp = tid >> 5, lane = tid & 31;
    int g = lane >> 2, t4 = lane & 3;
    int q0w = bx * AQ + warp * 16;

    __shared__ __align__(16) bf16 Kh_s[AKT * LDV];
    __shared__ __align__(16) bf16 Kl_s[AKT * LDV];
    __shared__ __align__(16) bf16 Vh_s[AKT * LDV];
    __shared__ __align__(16) bf16 Vl_s[AKT * LDV];
    uint32_t aKh = (uint32_t)__cvta_generic_to_shared(Kh_s);
    uint32_t aKl = (uint32_t)__cvta_generic_to_shared(Kl_s);
    uint32_t aVh = (uint32_t)__cvta_generic_to_shared(Vh_s);
    uint32_t aVl = (uint32_t)__cvta_generic_to_shared(Vl_s);

    uint32_t qh[4][4], ql[4][4];
    {
        const float* qbase = qkv + (size_t)(b * TT) * (3 * DD) + h * HDIM;
        const float* r0p = qbase + (size_t)(q0w + g) * (3 * DD);
        const float* r1p = qbase + (size_t)(q0w + g + 8) * (3 * DD);
#pragma unroll
        for (int c = 0; c < 4; c++) {
            float2 v00 = *(const float2*)(r0p + c * 16 + 2 * t4);
            float2 v10 = *(const float2*)(r1p + c * 16 + 2 * t4);
            float2 v01 = *(const float2*)(r0p + c * 16 + 2 * t4 + 8);
            float2 v11 = *(const float2*)(r1p + c * 16 + 2 * t4 + 8);
            split2u(v00.x * 0.125f, v00.y * 0.125f, qh[c][0], ql[c][0]);
            split2u(v10.x * 0.125f, v10.y * 0.125f, qh[c][1], ql[c][1]);
            split2u(v01.x * 0.125f, v01.y * 0.125f, qh[c][2], ql[c][2]);
            split2u(v11.x * 0.125f, v11.y * 0.125f, qh[c][3], ql[c][3]);
        }
    }

    float O[8][4];
#pragma unroll
    for (int j = 0; j < 8; j++)
#pragma unroll
        for (int r = 0; r < 4; r++) O[j][r] = 0.f;
    float m0 = NEGINF, m1 = NEGINF, l0 = 0.f, l1 = 0.f;

    int b_r = (lane >> 4) * 8 + (lane & 7);
    int b_c = ((lane >> 3) & 1) * 8;
    int v_r = (lane & 7) + ((lane >> 3) & 1) * 8;
    int v_c = (lane >> 4) * 8;

    const float* kb = qkv + (size_t)(b * TT) * (3 * DD) + DD + h * HDIM;
    const float* vb = kb + DD;

    int ntiles = bx * 2 + 2;
    for (int tile = 0; tile < ntiles; tile++) {
        int kt = tile * AKT;
        __syncthreads();
#pragma unroll
        for (int i = 0; i < 8; i++) {
            int cid = tid + i * 256;
            int kk = cid >> 5;
            int d2 = (cid & 31) * 2;
            const float* kr = kb + (size_t)(kt + kk) * (3 * DD) + d2;
            const float* vr = vb + (size_t)(kt + kk) * (3 * DD) + d2;
            float2 kv = *(const float2*)kr;
            float2 vv = *(const float2*)vr;
            uint32_t hh, ll;
            split2u(kv.x, kv.y, hh, ll);
            *(uint32_t*)(Kh_s + kk * LDV + d2) = hh;
            *(uint32_t*)(Kl_s + kk * LDV + d2) = ll;
            split2u(vv.x, vv.y, hh, ll);
            *(uint32_t*)(Vh_s + kk * LDV + d2) = hh;
            *(uint32_t*)(Vl_s + kk * LDV + d2) = ll;
        }
        __syncthreads();

        if (kt > q0w + 15) continue;

        float S[8][4];
#pragma unroll
        for (int j = 0; j < 8; j++)
#pragma unroll
            for (int r = 0; r < 4; r++) S[j][r] = 0.f;

#pragma unroll
        for (int c = 0; c < 4; c++) {
            uint32_t kf[8][2];
#pragma unroll
            for (int p = 0; p < 4; p++) {
                uint32_t r0, r1, r2, r3;
                ldm_x4(r0, r1, r2, r3, aKh + (uint32_t)((16 * p + b_r) * LDV + 16 * c + b_c) * 2);
                kf[2 * p][0] = r0; kf[2 * p][1] = r1;
                kf[2 * p + 1][0] = r2; kf[2 * p + 1][1] = r3;
            }
#pragma unroll
            for (int j = 0; j < 8; j++) mma16816(S[j], qh[c], kf[j]);
#pragma unroll
            for (int j = 0; j < 8; j++) mma16816(S[j], ql[c], kf[j]);
#pragma unroll
            for (int p = 0; p < 4; p++) {
                uint32_t r0, r1, r2, r3;
                ldm_x4(r0, r1, r2, r3, aKl + (uint32_t)((16 * p + b_r) * LDV + 16 * c + b_c) * 2);
                kf[2 * p][0] = r0; kf[2 * p][1] = r1;
                kf[2 * p + 1][0] = r2; kf[2 * p + 1][1] = r3;
            }
#pragma unroll
            for (int j = 0; j < 8; j++) mma16816(S[j], qh[c], kf[j]);
        }

        if (kt + AKT - 1 > q0w) {
            int row0 = q0w + g, row1 = q0w + g + 8;
#pragma unroll
            for (int j = 0; j < 8; j++) {
                int col = kt + 8 * j + 2 * t4;
                if (col > row0)     S[j][0] = NEGINF;
                if (col + 1 > row0) S[j][1] = NEGINF;
                if (col > row1)     S[j][2] = NEGINF;
                if (col + 1 > row1) S[j][3] = NEGINF;
            }
        }

        float mx0 = NEGINF, mx1 = NEGINF;
#pragma unroll
        for (int j = 0; j < 8; j++) {
            mx0 = fmaxf(mx0, fmaxf(S[j][0], S[j][1]));
            mx1 = fmaxf(mx1, fmaxf(S[j][2], S[j][3]));
        }
        mx0 = fmaxf(mx0, __shfl_xor_sync(0xffffffffu, mx0, 1));
        mx0 = fmaxf(mx0, __shfl_xor_sync(0xffffffffu, mx0, 2));
        mx1 = fmaxf(mx1, __shfl_xor_sync(0xffffffffu, mx1, 1));
        mx1 = fmaxf(mx1, __shfl_xor_sync(0xffffffffu, mx1, 2));
        float m0n = fmaxf(m0, mx0), m1n = fmaxf(m1, mx1);
        float c0 = __expf(m0 - m0n), c1 = __expf(m1 - m1n);
        float s0 = 0.f, s1 = 0.f;
#pragma unroll
        for (int j = 0; j < 8; j++) {
            S[j][0] = __expf(S[j][0] - m0n);
            S[j][1] = __expf(S[j][1] - m0n);
            S[j][2] = __expf(S[j][2] - m1n);
            S[j][3] = __expf(S[j][3] - m1n);
            s0 += S[j][0] + S[j][1];
            s1 += S[j][2] + S[j][3];
        }
        s0 += __shfl_xor_sync(0xffffffffu, s0, 1);
        s0 += __shfl_xor_sync(0xffffffffu, s0, 2);
        s1 += __shfl_xor_sync(0xffffffffu, s1, 1);
        s1 += __shfl_xor_sync(0xffffffffu, s1, 2);
        l0 = l0 * c0 + s0;
        l1 = l1 * c1 + s1;
        m0 = m0n; m1 = m1n;
#pragma unroll
        for (int j = 0; j < 8; j++) {
            O[j][0] *= c0; O[j][1] *= c0;
            O[j][2] *= c1; O[j][3] *= c1;
        }

#pragma unroll
        for (int kk = 0; kk < 4; kk++) {
            uint32_t ph[4], pl[4];
            split2u(S[2 * kk][0],     S[2 * kk][1],     ph[0], pl[0]);
            split2u(S[2 * kk][2],     S[2 * kk][3],     ph[1], pl[1]);
            split2u(S[2 * kk + 1][0], S[2 * kk + 1][1], ph[2], pl[2]);
            split2u(S[2 * kk + 1][2], S[2 * kk + 1][3], ph[3], pl[3]);

            uint32_t vf[8][2];
#pragma unroll
            for (int ds = 0; ds < 4; ds++) {
                uint32_t r0, r1, r2, r3;
                ldm_x4_t(r0, r1, r2, r3, aVh + (uint32_t)((16 * kk + v_r) * LDV + 16 * ds + v_c) * 2);
                vf[2 * ds][0] = r0; vf[2 * ds][1] = r1;
                vf[2 * ds + 1][0] = r2; vf[2 * ds + 1][1] = r3;
            }
#pragma unroll
            for (int j = 0; j < 8; j++) mma16816(O[j], ph, vf[j]);
#pragma unroll
            for (int j = 0; j < 8; j++) mma16816(O[j], pl, vf[j]);
#pragma unroll
            for (int ds = 0; ds < 4; ds++) {
                uint32_t r0, r1, r2, r3;
                ldm_x4_t(r0, r1, r2, r3, aVl + (uint32_t)((16 * kk + v_r) * LDV + 16 * ds + v_c) * 2);
                vf[2 * ds][0] = r0; vf[2 * ds][1] = r1;
                vf[2 * ds + 1][0] = r2; vf[2 * ds + 1][1] = r3;
            }
#pragma unroll
            for (int j = 0; j < 8; j++) mma16816(O[j], ph, vf[j]);
        }
    }

    float i0 = 1.f / l0, i1 = 1.f / l1;
    size_t off0 = (size_t)(b * TT + q0w + g) * DD + h * HDIM + 2 * t4;
    size_t off1 = (size_t)(b * TT + q0w + g + 8) * DD + h * HDIM + 2 * t4;
#pragma unroll
    for (int j = 0; j < 8; j++) {
        uint32_t hh, ll;
        split2u(O[j][0] * i0, O[j][1] * i0, hh, ll);
        *(uint32_t*)(yhi + off0 + 8 * j) = hh;
        *(uint32_t*)(ylo + off0 + 8 * j) = ll;
        split2u(O[j][2] * i1, O[j][3] * i1, hh, ll);
        *(uint32_t*)(yhi + off1 + 8 * j) = hh;
        *(uint32_t*)(ylo + off1 + 8 * j) = ll;
    }
}

// ---------------------------------------------------------------------------
// Host launcher
// ---------------------------------------------------------------------------
extern "C" void kernel_launch(void* const* d_in, const int* in_sizes, int n_in,
                              void* d_out, int out_size) {
    const int*   idx    = (const int*)  d_in[0];
    const float* wte    = (const float*)d_in[1];
    const float* wpe    = (const float*)d_in[2];
    const float* ln1_s  = (const float*)d_in[3];
    const float* ln1_b  = (const float*)d_in[4];
    const float* qkv_w  = (const float*)d_in[5];
    const float* proj_w = (const float*)d_in[6];
    const float* ln2_s  = (const float*)d_in[7];
    const float* ln2_b  = (const float*)d_in[8];
    const float* fc_w   = (const float*)d_in[9];
    const float* fc_b   = (const float*)d_in[10];
    const float* fc2_w  = (const float*)d_in[11];
    const float* fc2_b  = (const float*)d_in[12];
    const float* lnf_s  = (const float*)d_in[13];
    const float* lnf_b  = (const float*)d_in[14];
    const float* lm_w   = (const float*)d_in[15];
    float* out = (float*)d_out;

    float *x, *qkv;
    bf16 *h_hi, *h_lo, *y_hi, *y_lo, *gg_hi, *gg_lo;
    bf16 *qw_hi, *qw_lo, *pw_hi, *pw_lo, *fw_hi, *fw_lo, *f2_hi, *f2_lo, *lw_hi, *lw_lo;
    cudaGetSymbolAddress((void**)&x,     g_x);
    cudaGetSymbolAddress((void**)&qkv,   g_qkv);
    cudaGetSymbolAddress((void**)&h_hi,  g_h_hi);   cudaGetSymbolAddress((void**)&h_lo,  g_h_lo);
    cudaGetSymbolAddress((void**)&y_hi,  g_y_hi);   cudaGetSymbolAddress((void**)&y_lo,  g_y_lo);
    cudaGetSymbolAddress((void**)&gg_hi, g_g_hi);   cudaGetSymbolAddress((void**)&gg_lo, g_g_lo);
    cudaGetSymbolAddress((void**)&qw_hi, g_qkvw_hi); cudaGetSymbolAddress((void**)&qw_lo, g_qkvw_lo);
    cudaGetSymbolAddress((void**)&pw_hi, g_projw_hi); cudaGetSymbolAddress((void**)&pw_lo, g_projw_lo);
    cudaGetSymbolAddress((void**)&fw_hi, g_fcw_hi);  cudaGetSymbolAddress((void**)&fw_lo, g_fcw_lo);
    cudaGetSymbolAddress((void**)&f2_hi, g_fc2w_hi); cudaGetSymbolAddress((void**)&f2_lo, g_fc2w_lo);
    cudaGetSymbolAddress((void**)&lw_hi, g_lmw_hi);  cudaGetSymbolAddress((void**)&lw_lo, g_lmw_lo);

    cudaFuncSetAttribute(gemm3, cudaFuncAttributeMaxDynamicSharedMemorySize, GSM);

    embed_kernel<<<MM, 256>>>(idx, wte, wpe, x);

    {
        int nq = LL * 3 * DD * DD, np = LL * DD * DD;
        int nf = LL * 4 * DD * DD, n2 = LL * 4 * DD * DD, nl = VV * DD;
        int maxn = nf;
        dim3 grid((maxn / 4 + 255) / 256, 5);
        wsplit_all<<<grid, 256>>>(qkv_w,  qw_hi, qw_lo, nq,
                                  proj_w, pw_hi, pw_lo, np,
                                  fc_w,   fw_hi, fw_lo, nf,
                                  fc2_w,  f2_hi, f2_lo, n2,
                                  lm_w,   lw_hi, lw_lo, nl);
    }

    for (int l = 0; l < LL; l++) {
        bf16* qwh = qw_hi + (size_t)l * 3 * DD * DD;  bf16* qwl = qw_lo + (size_t)l * 3 * DD * DD;
        bf16* pwh = pw_hi + (size_t)l * DD * DD;      bf16* pwl = pw_lo + (size_t)l * DD * DD;
        bf16* fwh = fw_hi + (size_t)l * 4 * DD * DD;  bf16* fwl = fw_lo + (size_t)l * 4 * DD * DD;
        bf16* f2h = f2_hi + (size_t)l * 4 * DD * DD;  bf16* f2l = f2_lo + (size_t)l * 4 * DD * DD;
        const float* fb  = fc_b  + (size_t)l * 4 * DD;
        const float* f2b = fc2_b + (size_t)l * DD;

        ln_split_kernel<<<MM, 256>>>(x, ln1_s + l * DD, ln1_b + l * DD, h_hi, h_lo);
        gemm3<<<dim3(3 * DD / BN, MM / BM), 256, GSM>>>(h_hi, h_lo, qwh, qwl,
            nullptr, nullptr, qkv, nullptr, nullptr, MM, 3 * DD, DD, 0);
        attn_mma<<<dim3(TT / AQ, HH, BB), 256>>>(qkv, y_hi, y_lo);
        gemm3<<<dim3(DD / BN, MM / BM), 256, GSM>>>(y_hi, y_lo, pwh, pwl,
            nullptr, x, x, nullptr, nullptr, MM, DD, DD, FLAG_RES);
        ln_split_kernel<<<MM, 256>>>(x, ln2_s + l * DD, ln2_b + l * DD, h_hi, h_lo);
        gemm3<<<dim3(4 * DD / BN, MM / BM), 256, GSM>>>(h_hi, h_lo, fwh, fwl,
            fb, nullptr, nullptr, gg_hi, gg_lo, MM, 4 * DD, DD, FLAG_BIAS | FLAG_GELU | FLAG_SPLIT);
        gemm3<<<dim3(DD / BN, MM / BM), 256, GSM>>>(gg_hi, gg_lo, f2h, f2l,
            f2b, x, x, nullptr, nullptr, MM, DD, 4 * DD, FLAG_BIAS | FLAG_RES);
    }

    ln_split_kernel<<<MM, 256>>>(x, lnf_s, lnf_b, h_hi, h_lo);
    gemm3<<<dim3(VV / BN, MM / BM), 256, GSM>>>(h_hi, h_lo, lw_hi, lw_lo,
        nullptr, nullptr, out, nullptr, nullptr, MM, VV, DD, 0);
}

// round 9
// speedup vs baseline: 1.7550x; 1.0281x over previous
#include <cuda_runtime.h>
#include <cuda_bf16.h>
#include <math.h>
#include <stdint.h>

// Model dims
#define BB   2
#define TT   1024
#define DD   1024
#define HH   16
#define HDIM 64
#define LL   8
#define VV   32000
#define MM   (BB*TT)   // 2048 tokens

typedef __nv_bfloat16 bf16;
typedef __nv_bfloat162 bf162;

// GEMM tiling: CTA (MF*32)x128, warp (MF*16)x32, BK=32, 3-stage pipeline
#define BN 128
#define BK 32
#define NSTAGE 3

// Attention tiling
#define AQ  128
#define AKT 64
#define LDV 72
#define NEGINF (-1e30f)

// fp32 scratch
__device__ float g_x  [MM * DD];
__device__ float g_qkv[MM * 3 * DD];
// bf16 hi/lo activation scratch
__device__ bf16 g_h_hi[MM * DD],     g_h_lo[MM * DD];
__device__ bf16 g_y_hi[MM * DD],     g_y_lo[MM * DD];
__device__ bf16 g_g_hi[MM * 4 * DD], g_g_lo[MM * 4 * DD];
// bf16 hi/lo weight scratch
__device__ bf16 g_qkvw_hi[LL * 3 * DD * DD], g_qkvw_lo[LL * 3 * DD * DD];
__device__ bf16 g_projw_hi[LL * DD * DD],    g_projw_lo[LL * DD * DD];
__device__ bf16 g_fcw_hi [LL * 4 * DD * DD], g_fcw_lo [LL * 4 * DD * DD];
__device__ bf16 g_fc2w_hi[LL * 4 * DD * DD], g_fc2w_lo[LL * 4 * DD * DD];
__device__ bf16 g_lmw_hi [VV * DD],          g_lmw_lo [VV * DD];

// ---------------------------------------------------------------------------
// Small helpers
// ---------------------------------------------------------------------------
__device__ __forceinline__ void split2u(float x, float y, uint32_t& hi, uint32_t& lo) {
    bf162 hp, lp;
    hp.x = __float2bfloat16(x); hp.y = __float2bfloat16(y);
    lp.x = __float2bfloat16(x - __bfloat162float(hp.x));
    lp.y = __float2bfloat16(y - __bfloat162float(hp.y));
    hi = *(uint32_t*)&hp; lo = *(uint32_t*)&lp;
}

__device__ __forceinline__ void ldm_x4(uint32_t& r0, uint32_t& r1, uint32_t& r2, uint32_t& r3,
                                       uint32_t addr) {
    asm volatile("ldmatrix.sync.aligned.m8n8.x4.shared.b16 {%0,%1,%2,%3}, [%4];\n"
                 : "=r"(r0), "=r"(r1), "=r"(r2), "=r"(r3) : "r"(addr));
}

__device__ __forceinline__ void ldm_x4_t(uint32_t& r0, uint32_t& r1, uint32_t& r2, uint32_t& r3,
                                         uint32_t addr) {
    asm volatile("ldmatrix.sync.aligned.m8n8.x4.trans.shared.b16 {%0,%1,%2,%3}, [%4];\n"
                 : "=r"(r0), "=r"(r1), "=r"(r2), "=r"(r3) : "r"(addr));
}

__device__ __forceinline__ void mma16816(float* d, const uint32_t* a, const uint32_t* b) {
    asm volatile(
        "mma.sync.aligned.m16n8k16.row.col.f32.bf16.bf16.f32 "
        "{%0,%1,%2,%3}, {%4,%5,%6,%7}, {%8,%9}, {%0,%1,%2,%3};\n"
        : "+f"(d[0]), "+f"(d[1]), "+f"(d[2]), "+f"(d[3])
        : "r"(a[0]), "r"(a[1]), "r"(a[2]), "r"(a[3]), "r"(b[0]), "r"(b[1]));
}

__device__ __forceinline__ void cp16(uint32_t dst, const void* src) {
    asm volatile("cp.async.cg.shared.global [%0], [%1], 16;\n" :: "r"(dst), "l"(src));
}

// swizzled byte offset within one Rx32(bf16) tile: row r, 16B chunk c (0..3)
__device__ __forceinline__ uint32_t swz(int r, int c) {
    return (uint32_t)(r * 64 + ((c ^ ((r >> 1) & 3)) << 4));
}

// ---------------------------------------------------------------------------
// Fused weight split
// ---------------------------------------------------------------------------
__global__ void wsplit_all(const float* s0, bf16* h0, bf16* l0, int n0,
                           const float* s1, bf16* h1, bf16* l1, int n1,
                           const float* s2, bf16* h2, bf16* l2, int n2,
                           const float* s3, bf16* h3, bf16* l3, int n3,
                           const float* s4, bf16* h4, bf16* l4, int n4) {
    const float* src; bf16* hi; bf16* lo; int n;
    switch (blockIdx.y) {
        case 0: src = s0; hi = h0; lo = l0; n = n0; break;
        case 1: src = s1; hi = h1; lo = l1; n = n1; break;
        case 2: src = s2; hi = h2; lo = l2; n = n2; break;
        case 3: src = s3; hi = h3; lo = l3; n = n3; break;
        default: src = s4; hi = h4; lo = l4; n = n4; break;
    }
    int i = (blockIdx.x * blockDim.x + threadIdx.x) * 4;
    if (i >= n) return;
    float4 v = *(const float4*)(src + i);
    uint32_t hh, ll;
    split2u(v.x, v.y, hh, ll);
    ((uint32_t*)(hi + i))[0] = hh; ((uint32_t*)(lo + i))[0] = ll;
    split2u(v.z, v.w, hh, ll);
    ((uint32_t*)(hi + i))[1] = hh; ((uint32_t*)(lo + i))[1] = ll;
}

// ---------------------------------------------------------------------------
// Embedding
// ---------------------------------------------------------------------------
__global__ void embed_kernel(const int* __restrict__ idx,
                             const float* __restrict__ wte,
                             const float* __restrict__ wpe,
                             float* __restrict__ x) {
    int token = blockIdx.x;
    int t = token % TT;
    int id = idx[token];
    const float4* src = (const float4*)(wte + (size_t)id * DD);
    const float4* pos = (const float4*)(wpe + (size_t)t * DD);
    float4* dst = (float4*)(x + (size_t)token * DD);
    for (int i = threadIdx.x; i < DD / 4; i += blockDim.x) {
        float4 a = src[i], b = pos[i];
        dst[i] = make_float4(a.x + b.x, a.y + b.y, a.z + b.z, a.w + b.w);
    }
}

// ---------------------------------------------------------------------------
// LayerNorm over D=1024 -> bf16 hi/lo
// ---------------------------------------------------------------------------
__global__ __launch_bounds__(256) void ln_split_kernel(const float* __restrict__ x,
                                                       const float* __restrict__ sc,
                                                       const float* __restrict__ bi,
                                                       bf16* __restrict__ ohi,
                                                       bf16* __restrict__ olo) {
    int token = blockIdx.x;
    const float4* xp = (const float4*)(x + (size_t)token * DD);
    float4 v = xp[threadIdx.x];
    float s = v.x + v.y + v.z + v.w;
    float q = v.x * v.x + v.y * v.y + v.z * v.z + v.w * v.w;
#pragma unroll
    for (int o = 16; o; o >>= 1) {
        s += __shfl_xor_sync(0xffffffffu, s, o);
        q += __shfl_xor_sync(0xffffffffu, q, o);
    }
    __shared__ float ss[8], sq[8];
    int w = threadIdx.x >> 5, l = threadIdx.x & 31;
    if (l == 0) { ss[w] = s; sq[w] = q; }
    __syncthreads();
    if (w == 0) {
        s = (l < 8) ? ss[l] : 0.f;
        q = (l < 8) ? sq[l] : 0.f;
#pragma unroll
        for (int o = 4; o; o >>= 1) {
            s += __shfl_xor_sync(0xffffffffu, s, o);
            q += __shfl_xor_sync(0xffffffffu, q, o);
        }
        if (l == 0) { ss[0] = s; sq[0] = q; }
    }
    __syncthreads();
    float mu  = ss[0] * (1.f / DD);
    float var = sq[0] * (1.f / DD) - mu * mu;
    float inv = rsqrtf(var + 1e-5f);
    float4 sv = ((const float4*)sc)[threadIdx.x];
    float4 bv = ((const float4*)bi)[threadIdx.x];
    float r0 = (v.x - mu) * inv * sv.x + bv.x;
    float r1 = (v.y - mu) * inv * sv.y + bv.y;
    float r2 = (v.z - mu) * inv * sv.z + bv.z;
    float r3 = (v.w - mu) * inv * sv.w + bv.w;
    size_t o = (size_t)token * DD + threadIdx.x * 4;
    uint32_t hh, ll;
    split2u(r0, r1, hh, ll);
    ((uint32_t*)(ohi + o))[0] = hh; ((uint32_t*)(olo + o))[0] = ll;
    split2u(r2, r3, hh, ll);
    ((uint32_t*)(ohi + o))[1] = hh; ((uint32_t*)(olo + o))[1] = ll;
}

// ---------------------------------------------------------------------------
// Templated tensor-core GEMM NT: CTA (MF*32)x128, warp (MF*16)x32, BK=32,
// 3-pass bf16-split, 3-stage cp.async pipeline, swizzled smem, one barrier.
// ---------------------------------------------------------------------------
#define FLAG_BIAS  1
#define FLAG_RES   2
#define FLAG_GELU  4
#define FLAG_SPLIT 8

__device__ __forceinline__ float gelu_exact(float v) {
    return 0.5f * v * (1.f + erff(v * 0.70710678118654752f));
}

template<int MF>
__global__ __launch_bounds__(256) void gemm3t(const bf16* __restrict__ Ah,
                                              const bf16* __restrict__ Al,
                                              const bf16* __restrict__ Bh,
                                              const bf16* __restrict__ Bl,
                                              const float* __restrict__ bias,
                                              const float* res,
                                              float* C, bf16* Chi, bf16* Clo,
                                              int M, int N, int K, int flags) {
    constexpr int BMT   = MF * 32;            // CTA M tile
    constexpr int TILEA = BMT * 64;           // bytes per A tile (BMT rows x 64B)
    constexpr int TILEBB = 8192;              // bytes per B tile (128 rows x 64B)
    constexpr int BUFB  = 2 * TILEA + 2 * TILEBB;
    constexpr int NCHUNK = (2 * BMT * 4 + 2 * 512) / 256;  // cp.async per thread

    extern __shared__ __align__(16) bf16 sm[];
    int tid = threadIdx.x;
    int warp = tid >> 5, lane = tid & 31;
    int bm = blockIdx.y * BMT, bn = blockIdx.x * BN;
    int wm = (warp >> 2) * (MF * 16);
    int wn = (warp & 3) * 32;

    uint32_t smbase = (uint32_t)__cvta_generic_to_shared(sm);

    float acc[MF][4][4];
#pragma unroll
    for (int i = 0; i < MF; i++)
#pragma unroll
        for (int j = 0; j < 4; j++)
#pragma unroll
            for (int r = 0; r < 4; r++) acc[i][j][r] = 0.f;

    int a_r = ((lane >> 3) & 1) * 8 + (lane & 7);
    int a_c = (lane >> 4) * 8;
    int b_r = (lane >> 4) * 8 + (lane & 7);
    int b_c = ((lane >> 3) & 1) * 8;

    const bf16* srcA[2] = { Ah, Al };
    const bf16* srcB[2] = { Bh, Bl };

    auto stage = [&](int s_idx, int buf) {
        int k0 = s_idx * BK;
        uint32_t bufoff = smbase + (uint32_t)(buf * BUFB);
#pragma unroll
        for (int i = 0; i < NCHUNK; i++) {
            int cid = tid + i * 256;
            if (cid < 2 * BMT * 4) {           // A region
                int arr = cid / (BMT * 4);
                int sub = cid - arr * (BMT * 4);
                int row = sub >> 2;
                int c = sub & 3;
                const bf16* src = srcA[arr] + (size_t)(bm + row) * K + k0 + c * 8;
                cp16(bufoff + (uint32_t)(arr * TILEA) + swz(row, c), src);
            } else {                            // B region
                int cidB = cid - 2 * BMT * 4;
                int arr = cidB >> 9;
                int sub = cidB & 511;
                int row = sub >> 2;
                int c = sub & 3;
                const bf16* src = srcB[arr] + (size_t)(bn + row) * K + k0 + c * 8;
                cp16(bufoff + (uint32_t)(2 * TILEA + arr * TILEBB) + swz(row, c), src);
            }
        }
        asm volatile("cp.async.commit_group;\n");
    };

    int S = K / BK;
    stage(0, 0);
    stage(1, 1);

    for (int s = 0; s < S; s++) {
        int buf = s - (s / NSTAGE) * NSTAGE;
        if (s == S - 1) asm volatile("cp.async.wait_group 0;\n");
        else            asm volatile("cp.async.wait_group 1;\n");
        __syncthreads();
        if (s + 2 < S) stage(s + 2, (s + 2) % NSTAGE);

        uint32_t offAh = smbase + (uint32_t)(buf * BUFB);
        uint32_t offAl = offAh + TILEA;
        uint32_t offBh = offAl + TILEA;
        uint32_t offBl = offBh + TILEBB;

#pragma unroll
        for (int ks = 0; ks < BK; ks += 16) {
            uint32_t ah[MF][4], al[MF][4], bh[4][2], bl[4][2];
#pragma unroll
            for (int mf = 0; mf < MF; mf++) {
                int row = wm + mf * 16 + a_r;
                ldm_x4(ah[mf][0], ah[mf][1], ah[mf][2], ah[mf][3],
                       offAh + swz(row, (ks + a_c) >> 3));
            }
#pragma unroll
            for (int p = 0; p < 2; p++) {
                int row = wn + p * 16 + b_r;
                uint32_t r0, r1, r2, r3;
                ldm_x4(r0, r1, r2, r3, offBh + swz(row, (ks + b_c) >> 3));
                bh[2 * p][0] = r0; bh[2 * p][1] = r1;
                bh[2 * p + 1][0] = r2; bh[2 * p + 1][1] = r3;
            }
#pragma unroll
            for (int mf = 0; mf < MF; mf++)
#pragma unroll
                for (int nf = 0; nf < 4; nf++)
                    mma16816(acc[mf][nf], ah[mf], bh[nf]);

#pragma unroll
            for (int p = 0; p < 2; p++) {
                int row = wn + p * 16 + b_r;
                uint32_t r0, r1, r2, r3;
                ldm_x4(r0, r1, r2, r3, offBl + swz(row, (ks + b_c) >> 3));
                bl[2 * p][0] = r0; bl[2 * p][1] = r1;
                bl[2 * p + 1][0] = r2; bl[2 * p + 1][1] = r3;
            }
#pragma unroll
            for (int mf = 0; mf < MF; mf++)
#pragma unroll
                for (int nf = 0; nf < 4; nf++)
                    mma16816(acc[mf][nf], ah[mf], bl[nf]);

#pragma unroll
            for (int mf = 0; mf < MF; mf++) {
                int row = wm + mf * 16 + a_r;
                ldm_x4(al[mf][0], al[mf][1], al[mf][2], al[mf][3],
                       offAl + swz(row, (ks + a_c) >> 3));
            }
#pragma unroll
            for (int mf = 0; mf < MF; mf++)
#pragma unroll
                for (int nf = 0; nf < 4; nf++)
                    mma16816(acc[mf][nf], al[mf], bh[nf]);
        }
    }

    int gid = lane >> 2, tg = lane & 3;
#pragma unroll
    for (int mf = 0; mf < MF; mf++) {
#pragma unroll
        for (int half = 0; half < 2; half++) {
            int row = bm + wm + mf * 16 + half * 8 + gid;
#pragma unroll
            for (int nf = 0; nf < 4; nf++) {
                int col = bn + wn + nf * 8 + tg * 2;
                float2 o;
                o.x = acc[mf][nf][half * 2 + 0];
                o.y = acc[mf][nf][half * 2 + 1];
                if (flags & FLAG_BIAS) { o.x += bias[col]; o.y += bias[col + 1]; }
                if (flags & FLAG_GELU) { o.x = gelu_exact(o.x); o.y = gelu_exact(o.y); }
                if (flags & FLAG_RES) {
                    float2 r = *(const float2*)(res + (size_t)row * N + col);
                    o.x += r.x; o.y += r.y;
                }
                if (flags & FLAG_SPLIT) {
                    size_t off = (size_t)row * N + col;
                    uint32_t hh, ll;
                    split2u(o.x, o.y, hh, ll);
                    *(uint32_t*)(Chi + off) = hh;
                    *(uint32_t*)(Clo + off) = ll;
                } else {
                    *(float2*)(C + (size_t)row * N + col) = o;
                }
            }
        }
    }
}

// GSM per MF
#define GSM_MF2 (NSTAGE * (2 * 64 * 64 + 2 * 8192))    // 73728
#define GSM_MF4 (NSTAGE * (2 * 128 * 64 + 2 * 8192))   // 98304

// ---------------------------------------------------------------------------
// Causal attention via mma.sync (flash-attention, bf16-split fp32-accurate).
// ---------------------------------------------------------------------------
__global__ __launch_bounds__(256) void attn_mma(const float* __restrict__ qkv,
                                                bf16* __restrict__ yhi,
                                                bf16* __restrict__ ylo) {
    int b = blockIdx.z, h = blockIdx.y;
    int bx = gridDim.x - 1 - blockIdx.x;
    int tid = threadIdx.x;
    int warp = tid >> 5, lane = tid & 31;
    int g = lane >> 2, t4 = lane & 3;
    int q0w = bx * AQ + warp * 16;

    __shared__ __align__(16) bf16 Kh_s[AKT * LDV];
    __shared__ __align__(16) bf16 Kl_s[AKT * LDV];
    __shared__ __align__(16) bf16 Vh_s[AKT * LDV];
    __shared__ __align__(16) bf16 Vl_s[AKT * LDV];
    uint32_t aKh = (uint32_t)__cvta_generic_to_shared(Kh_s);
    uint32_t aKl = (uint32_t)__cvta_generic_to_shared(Kl_s);
    uint32_t aVh = (uint32_t)__cvta_generic_to_shared(Vh_s);
    uint32_t aVl = (uint32_t)__cvta_generic_to_shared(Vl_s);

    uint32_t qh[4][4], ql[4][4];
    {
        const float* qbase = qkv + (size_t)(b * TT) * (3 * DD) + h * HDIM;
        const float* r0p = qbase + (size_t)(q0w + g) * (3 * DD);
        const float* r1p = qbase + (size_t)(q0w + g + 8) * (3 * DD);
#pragma unroll
        for (int c = 0; c < 4; c++) {
            float2 v00 = *(const float2*)(r0p + c * 16 + 2 * t4);
            float2 v10 = *(const float2*)(r1p + c * 16 + 2 * t4);
            float2 v01 = *(const float2*)(r0p + c * 16 + 2 * t4 + 8);
            float2 v11 = *(const float2*)(r1p + c * 16 + 2 * t4 + 8);
            split2u(v00.x * 0.125f, v00.y * 0.125f, qh[c][0], ql[c][0]);
            split2u(v10.x * 0.125f, v10.y * 0.125f, qh[c][1], ql[c][1]);
            split2u(v01.x * 0.125f, v01.y * 0.125f, qh[c][2], ql[c][2]);
            split2u(v11.x * 0.125f, v11.y * 0.125f, qh[c][3], ql[c][3]);
        }
    }

    float O[8][4];
#pragma unroll
    for (int j = 0; j < 8; j++)
#pragma unroll
        for (int r = 0; r < 4; r++) O[j][r] = 0.f;
    float m0 = NEGINF, m1 = NEGINF, l0 = 0.f, l1 = 0.f;

    int b_r = (lane >> 4) * 8 + (lane & 7);
    int b_c = ((lane >> 3) & 1) * 8;
    int v_r = (lane & 7) + ((lane >> 3) & 1) * 8;
    int v_c = (lane >> 4) * 8;

    const float* kb = qkv + (size_t)(b * TT) * (3 * DD) + DD + h * HDIM;
    const float* vb = kb + DD;

    int ntiles = bx * 2 + 2;
    for (int tile = 0; tile < ntiles; tile++) {
        int kt = tile * AKT;
        __syncthreads();
#pragma unroll
        for (int i = 0; i < 8; i++) {
            int cid = tid + i * 256;
            int kk = cid >> 5;
            int d2 = (cid & 31) * 2;
            const float* kr = kb + (size_t)(kt + kk) * (3 * DD) + d2;
            const float* vr = vb + (size_t)(kt + kk) * (3 * DD) + d2;
            float2 kv = *(const float2*)kr;
            float2 vv = *(const float2*)vr;
            uint32_t hh, ll;
            split2u(kv.x, kv.y, hh, ll);
            *(uint32_t*)(Kh_s + kk * LDV + d2) = hh;
            *(uint32_t*)(Kl_s + kk * LDV + d2) = ll;
            split2u(vv.x, vv.y, hh, ll);
            *(uint32_t*)(Vh_s + kk * LDV + d2) = hh;
            *(uint32_t*)(Vl_s + kk * LDV + d2) = ll;
        }
        __syncthreads();

        if (kt > q0w + 15) continue;

        float S[8][4];
#pragma unroll
        for (int j = 0; j < 8; j++)
#pragma unroll
            for (int r = 0; r < 4; r++) S[j][r] = 0.f;

#pragma unroll
        for (int c = 0; c < 4; c++) {
            uint32_t kf[8][2];
#pragma unroll
            for (int p = 0; p < 4; p++) {
                uint32_t r0, r1, r2, r3;
                ldm_x4(r0, r1, r2, r3, aKh + (uint32_t)((16 * p + b_r) * LDV + 16 * c + b_c) * 2);
                kf[2 * p][0] = r0; kf[2 * p][1] = r1;
                kf[2 * p + 1][0] = r2; kf[2 * p + 1][1] = r3;
            }
#pragma unroll
            for (int j = 0; j < 8; j++) mma16816(S[j], qh[c], kf[j]);
#pragma unroll
            for (int j = 0; j < 8; j++) mma16816(S[j], ql[c], kf[j]);
#pragma unroll
            for (int p = 0; p < 4; p++) {
                uint32_t r0, r1, r2, r3;
                ldm_x4(r0, r1, r2, r3, aKl + (uint32_t)((16 * p + b_r) * LDV + 16 * c + b_c) * 2);
                kf[2 * p][0] = r0; kf[2 * p][1] = r1;
                kf[2 * p + 1][0] = r2; kf[2 * p + 1][1] = r3;
            }
#pragma unroll
            for (int j = 0; j < 8; j++) mma16816(S[j], qh[c], kf[j]);
        }

        if (kt + AKT - 1 > q0w) {
            int row0 = q0w + g, row1 = q0w + g + 8;
#pragma unroll
            for (int j = 0; j < 8; j++) {
                int col = kt + 8 * j + 2 * t4;
                if (col > row0)     S[j][0] = NEGINF;
                if (col + 1 > row0) S[j][1] = NEGINF;
                if (col > row1)     S[j][2] = NEGINF;
                if (col + 1 > row1) S[j][3] = NEGINF;
            }
        }

        float mx0 = NEGINF, mx1 = NEGINF;
#pragma unroll
        for (int j = 0; j < 8; j++) {
            mx0 = fmaxf(mx0, fmaxf(S[j][0], S[j][1]));
            mx1 = fmaxf(mx1, fmaxf(S[j][2], S[j][3]));
        }
        mx0 = fmaxf(mx0, __shfl_xor_sync(0xffffffffu, mx0, 1));
        mx0 = fmaxf(mx0, __shfl_xor_sync(0xffffffffu, mx0, 2));
        mx1 = fmaxf(mx1, __shfl_xor_sync(0xffffffffu, mx1, 1));
        mx1 = fmaxf(mx1, __shfl_xor_sync(0xffffffffu, mx1, 2));
        float m0n = fmaxf(m0, mx0), m1n = fmaxf(m1, mx1);
        float c0 = __expf(m0 - m0n), c1 = __expf(m1 - m1n);
        float s0 = 0.f, s1 = 0.f;
#pragma unroll
        for (int j = 0; j < 8; j++) {
            S[j][0] = __expf(S[j][0] - m0n);
            S[j][1] = __expf(S[j][1] - m0n);
            S[j][2] = __expf(S[j][2] - m1n);
            S[j][3] = __expf(S[j][3] - m1n);
            s0 += S[j][0] + S[j][1];
            s1 += S[j][2] + S[j][3];
        }
        s0 += __shfl_xor_sync(0xffffffffu, s0, 1);
        s0 += __shfl_xor_sync(0xffffffffu, s0, 2);
        s1 += __shfl_xor_sync(0xffffffffu, s1, 1);
        s1 += __shfl_xor_sync(0xffffffffu, s1, 2);
        l0 = l0 * c0 + s0;
        l1 = l1 * c1 + s1;
        m0 = m0n; m1 = m1n;
#pragma unroll
        for (int j = 0; j < 8; j++) {
            O[j][0] *= c0; O[j][1] *= c0;
            O[j][2] *= c1; O[j][3] *= c1;
        }

#pragma unroll
        for (int kk = 0; kk < 4; kk++) {
            uint32_t ph[4], pl[4];
            split2u(S[2 * kk][0],     S[2 * kk][1],     ph[0], pl[0]);
            split2u(S[2 * kk][2],     S[2 * kk][3],     ph[1], pl[1]);
            split2u(S[2 * kk + 1][0], S[2 * kk + 1][1], ph[2], pl[2]);
            split2u(S[2 * kk + 1][2], S[2 * kk + 1][3], ph[3], pl[3]);

            uint32_t vf[8][2];
#pragma unroll
            for (int ds = 0; ds < 4; ds++) {
                uint32_t r0, r1, r2, r3;
                ldm_x4_t(r0, r1, r2, r3, aVh + (uint32_t)((16 * kk + v_r) * LDV + 16 * ds + v_c) * 2);
                vf[2 * ds][0] = r0; vf[2 * ds][1] = r1;
                vf[2 * ds + 1][0] = r2; vf[2 * ds + 1][1] = r3;
            }
#pragma unroll
            for (int j = 0; j < 8; j++) mma16816(O[j], ph, vf[j]);
#pragma unroll
            for (int j = 0; j < 8; j++) mma16816(O[j], pl, vf[j]);
#pragma unroll
            for (int ds = 0; ds < 4; ds++) {
                uint32_t r0, r1, r2, r3;
                ldm_x4_t(r0, r1, r2, r3, aVl + (uint32_t)((16 * kk + v_r) * LDV + 16 * ds + v_c) * 2);
                vf[2 * ds][0] = r0; vf[2 * ds][1] = r1;
                vf[2 * ds + 1][0] = r2; vf[2 * ds + 1][1] = r3;
            }
#pragma unroll
            for (int j = 0; j < 8; j++) mma16816(O[j], ph, vf[j]);
        }
    }

    float i0 = 1.f / l0, i1 = 1.f / l1;
    size_t off0 = (size_t)(b * TT + q0w + g) * DD + h * HDIM + 2 * t4;
    size_t off1 = (size_t)(b * TT + q0w + g + 8) * DD + h * HDIM + 2 * t4;
#pragma unroll
    for (int j = 0; j < 8; j++) {
        uint32_t hh, ll;
        split2u(O[j][0] * i0, O[j][1] * i0, hh, ll);
        *(uint32_t*)(yhi + off0 + 8 * j) = hh;
        *(uint32_t*)(ylo + off0 + 8 * j) = ll;
        split2u(O[j][2] * i1, O[j][3] * i1, hh, ll);
        *(uint32_t*)(yhi + off1 + 8 * j) = hh;
        *(uint32_t*)(ylo + off1 + 8 * j) = ll;
    }
}

// ---------------------------------------------------------------------------
// Host launcher
// ---------------------------------------------------------------------------
extern "C" void kernel_launch(void* const* d_in, const int* in_sizes, int n_in,
                              void* d_out, int out_size) {
    const int*   idx    = (const int*)  d_in[0];
    const float* wte    = (const float*)d_in[1];
    const float* wpe    = (const float*)d_in[2];
    const float* ln1_s  = (const float*)d_in[3];
    const float* ln1_b  = (const float*)d_in[4];
    const float* qkv_w  = (const float*)d_in[5];
    const float* proj_w = (const float*)d_in[6];
    const float* ln2_s  = (const float*)d_in[7];
    const float* ln2_b  = (const float*)d_in[8];
    const float* fc_w   = (const float*)d_in[9];
    const float* fc_b   = (const float*)d_in[10];
    const float* fc2_w  = (const float*)d_in[11];
    const float* fc2_b  = (const float*)d_in[12];
    const float* lnf_s  = (const float*)d_in[13];
    const float* lnf_b  = (const float*)d_in[14];
    const float* lm_w   = (const float*)d_in[15];
    float* out = (float*)d_out;

    float *x, *qkv;
    bf16 *h_hi, *h_lo, *y_hi, *y_lo, *gg_hi, *gg_lo;
    bf16 *qw_hi, *qw_lo, *pw_hi, *pw_lo, *fw_hi, *fw_lo, *f2_hi, *f2_lo, *lw_hi, *lw_lo;
    cudaGetSymbolAddress((void**)&x,     g_x);
    cudaGetSymbolAddress((void**)&qkv,   g_qkv);
    cudaGetSymbolAddress((void**)&h_hi,  g_h_hi);   cudaGetSymbolAddress((void**)&h_lo,  g_h_lo);
    cudaGetSymbolAddress((void**)&y_hi,  g_y_hi);   cudaGetSymbolAddress((void**)&y_lo,  g_y_lo);
    cudaGetSymbolAddress((void**)&gg_hi, g_g_hi);   cudaGetSymbolAddress((void**)&gg_lo, g_g_lo);
    cudaGetSymbolAddress((void**)&qw_hi, g_qkvw_hi); cudaGetSymbolAddress((void**)&qw_lo, g_qkvw_lo);
    cudaGetSymbolAddress((void**)&pw_hi, g_projw_hi); cudaGetSymbolAddress((void**)&pw_lo, g_projw_lo);
    cudaGetSymbolAddress((void**)&fw_hi, g_fcw_hi);  cudaGetSymbolAddress((void**)&fw_lo, g_fcw_lo);
    cudaGetSymbolAddress((void**)&f2_hi, g_fc2w_hi); cudaGetSymbolAddress((void**)&f2_lo, g_fc2w_lo);
    cudaGetSymbolAddress((void**)&lw_hi, g_lmw_hi);  cudaGetSymbolAddress((void**)&lw_lo, g_lmw_lo);

    cudaFuncSetAttribute(gemm3t<2>, cudaFuncAttributeMaxDynamicSharedMemorySize, GSM_MF2);
    cudaFuncSetAttribute(gemm3t<4>, cudaFuncAttributeMaxDynamicSharedMemorySize, GSM_MF4);

    embed_kernel<<<MM, 256>>>(idx, wte, wpe, x);

    {
        int nq = LL * 3 * DD * DD, np = LL * DD * DD;
        int nf = LL * 4 * DD * DD, n2 = LL * 4 * DD * DD, nl = VV * DD;
        int maxn = nf;
        dim3 grid((maxn / 4 + 255) / 256, 5);
        wsplit_all<<<grid, 256>>>(qkv_w,  qw_hi, qw_lo, nq,
                                  proj_w, pw_hi, pw_lo, np,
                                  fc_w,   fw_hi, fw_lo, nf,
                                  fc2_w,  f2_hi, f2_lo, n2,
                                  lm_w,   lw_hi, lw_lo, nl);
    }

    for (int l = 0; l < LL; l++) {
        bf16* qwh = qw_hi + (size_t)l * 3 * DD * DD;  bf16* qwl = qw_lo + (size_t)l * 3 * DD * DD;
        bf16* pwh = pw_hi + (size_t)l * DD * DD;      bf16* pwl = pw_lo + (size_t)l * DD * DD;
        bf16* fwh = fw_hi + (size_t)l * 4 * DD * DD;  bf16* fwl = fw_lo + (size_t)l * 4 * DD * DD;
        bf16* f2h = f2_hi + (size_t)l * 4 * DD * DD;  bf16* f2l = f2_lo + (size_t)l * 4 * DD * DD;
        const float* fb  = fc_b  + (size_t)l * 4 * DD;
        const float* f2b = fc2_b + (size_t)l * DD;

        ln_split_kernel<<<MM, 256>>>(x, ln1_s + l * DD, ln1_b + l * DD, h_hi, h_lo);
        // qkv: [2048 x 3072], K=1024 -> MF=2, grid 24x32 = 768
        gemm3t<2><<<dim3(3 * DD / BN, MM / 64), 256, GSM_MF2>>>(h_hi, h_lo, qwh, qwl,
            nullptr, nullptr, qkv, nullptr, nullptr, MM, 3 * DD, DD, 0);
        attn_mma<<<dim3(TT / AQ, HH, BB), 256>>>(qkv, y_hi, y_lo);
        // proj: [2048 x 1024], K=1024 -> MF=2, grid 8x32 = 256
        gemm3t<2><<<dim3(DD / BN, MM / 64), 256, GSM_MF2>>>(y_hi, y_lo, pwh, pwl,
            nullptr, x, x, nullptr, nullptr, MM, DD, DD, FLAG_RES);
        ln_split_kernel<<<MM, 256>>>(x, ln2_s + l * DD, ln2_b + l * DD, h_hi, h_lo);
        // fc: [2048 x 4096], K=1024 -> MF=4, grid 32x16 = 512
        gemm3t<4><<<dim3(4 * DD / BN, MM / 128), 256, GSM_MF4>>>(h_hi, h_lo, fwh, fwl,
            fb, nullptr, nullptr, gg_hi, gg_lo, MM, 4 * DD, DD, FLAG_BIAS | FLAG_GELU | FLAG_SPLIT);
        // fc2: [2048 x 1024], K=4096 -> MF=2, grid 8x32 = 256
        gemm3t<2><<<dim3(DD / BN, MM / 64), 256, GSM_MF2>>>(gg_hi, gg_lo, f2h, f2l,
            f2b, x, x, nullptr, nullptr, MM, DD, 4 * DD, FLAG_BIAS | FLAG_RES);
    }

    ln_split_kernel<<<MM, 256>>>(x, lnf_s, lnf_b, h_hi, h_lo);
    // lm: [2048 x 32000], K=1024 -> MF=4, grid 250x16 = 4000
    gemm3t<4><<<dim3(VV / BN, MM / 128), 256, GSM_MF4>>>(h_hi, h_lo, lw_hi, lw_lo,
        nullptr, nullptr, out, nullptr, nullptr, MM, VV, DD, 0);
}

// round 10
// speedup vs baseline: 1.9309x; 1.1003x over previous
#include <cuda_runtime.h>
#include <cuda_bf16.h>
#include <cuda_fp16.h>
#include <math.h>
#include <stdint.h>

// Model dims
#define BB   2
#define TT   1024
#define DD   1024
#define HH   16
#define HDIM 64
#define LL   8
#define VV   32000
#define MM   (BB*TT)   // 2048 tokens

typedef __nv_bfloat16 bf16;
typedef __nv_bfloat162 bf162;

// GEMM tiling
#define BN 128
#define BK 32
#define NSTAGE 3

// Attention tiling
#define AQ  128
#define AKT 64
#define LDV 72
#define NEGINF (-1e30f)

// fp32 scratch
__device__ float g_x  [MM * DD];
__device__ float g_qkv[MM * 3 * DD];
// 16-bit activation scratch (bf16 or fp16 depending on consumer)
__device__ bf16 g_h_hi[MM * DD],     g_h_lo[MM * DD];
__device__ bf16 g_y_hi[MM * DD],     g_y_lo[MM * DD];
__device__ bf16 g_g_hi[MM * 4 * DD], g_g_lo[MM * 4 * DD];   // fp16 payload
// weight scratch
__device__ bf16 g_qkvw_hi[LL * 3 * DD * DD], g_qkvw_lo[LL * 3 * DD * DD];
__device__ bf16 g_projw_hi[LL * DD * DD],    g_projw_lo[LL * DD * DD];
__device__ bf16 g_fcw_hi [LL * 4 * DD * DD], g_fcw_lo [LL * 4 * DD * DD];
__device__ bf16 g_fc2w_hi[LL * 4 * DD * DD];                 // fp16 payload, single
__device__ bf16 g_lmw_hi [VV * DD];                          // fp16 payload, single

// ---------------------------------------------------------------------------
// Small helpers
// ---------------------------------------------------------------------------
__device__ __forceinline__ void split2u(float x, float y, uint32_t& hi, uint32_t& lo) {
    bf162 hp, lp;
    hp.x = __float2bfloat16(x); hp.y = __float2bfloat16(y);
    lp.x = __float2bfloat16(x - __bfloat162float(hp.x));
    lp.y = __float2bfloat16(y - __bfloat162float(hp.y));
    hi = *(uint32_t*)&hp; lo = *(uint32_t*)&lp;
}

__device__ __forceinline__ void split2h(float x, float y, uint32_t& hi, uint32_t& lo) {
    __half2 hp, lp;
    hp.x = __float2half_rn(x); hp.y = __float2half_rn(y);
    lp.x = __float2half_rn(x - __half2float(hp.x));
    lp.y = __float2half_rn(y - __half2float(hp.y));
    hi = *(uint32_t*)&hp; lo = *(uint32_t*)&lp;
}

__device__ __forceinline__ void ldm_x4(uint32_t& r0, uint32_t& r1, uint32_t& r2, uint32_t& r3,
                                       uint32_t addr) {
    asm volatile("ldmatrix.sync.aligned.m8n8.x4.shared.b16 {%0,%1,%2,%3}, [%4];\n"
                 : "=r"(r0), "=r"(r1), "=r"(r2), "=r"(r3) : "r"(addr));
}

__device__ __forceinline__ void ldm_x4_t(uint32_t& r0, uint32_t& r1, uint32_t& r2, uint32_t& r3,
                                         uint32_t addr) {
    asm volatile("ldmatrix.sync.aligned.m8n8.x4.trans.shared.b16 {%0,%1,%2,%3}, [%4];\n"
                 : "=r"(r0), "=r"(r1), "=r"(r2), "=r"(r3) : "r"(addr));
}

__device__ __forceinline__ void mma16816(float* d, const uint32_t* a, const uint32_t* b) {
    asm volatile(
        "mma.sync.aligned.m16n8k16.row.col.f32.bf16.bf16.f32 "
        "{%0,%1,%2,%3}, {%4,%5,%6,%7}, {%8,%9}, {%0,%1,%2,%3};\n"
        : "+f"(d[0]), "+f"(d[1]), "+f"(d[2]), "+f"(d[3])
        : "r"(a[0]), "r"(a[1]), "r"(a[2]), "r"(a[3]), "r"(b[0]), "r"(b[1]));
}

__device__ __forceinline__ void mma16816h(float* d, const uint32_t* a, const uint32_t* b) {
    asm volatile(
        "mma.sync.aligned.m16n8k16.row.col.f32.f16.f16.f32 "
        "{%0,%1,%2,%3}, {%4,%5,%6,%7}, {%8,%9}, {%0,%1,%2,%3};\n"
        : "+f"(d[0]), "+f"(d[1]), "+f"(d[2]), "+f"(d[3])
        : "r"(a[0]), "r"(a[1]), "r"(a[2]), "r"(a[3]), "r"(b[0]), "r"(b[1]));
}

__device__ __forceinline__ void cp16(uint32_t dst, const void* src) {
    asm volatile("cp.async.cg.shared.global [%0], [%1], 16;\n" :: "r"(dst), "l"(src));
}

// swizzled byte offset within one Rx32(16-bit) tile: row r, 16B chunk c (0..3)
__device__ __forceinline__ uint32_t swz(int r, int c) {
    return (uint32_t)(r * 64 + ((c ^ ((r >> 1) & 3)) << 4));
}

// ---------------------------------------------------------------------------
// Fused weight split. Cases 0-2: bf16 hi/lo. Cases 3-4: fp16 single.
// ---------------------------------------------------------------------------
__global__ void wsplit_all(const float* s0, bf16* h0, bf16* l0, int n0,
                           const float* s1, bf16* h1, bf16* l1, int n1,
                           const float* s2, bf16* h2, bf16* l2, int n2,
                           const float* s3, bf16* h3, int n3,
                           const float* s4, bf16* h4, int n4) {
    int i = (blockIdx.x * blockDim.x + threadIdx.x) * 4;
    if (blockIdx.y >= 3) {
        const float* src = (blockIdx.y == 3) ? s3 : s4;
        __half* hi = (__half*)((blockIdx.y == 3) ? h3 : h4);
        int n = (blockIdx.y == 3) ? n3 : n4;
        if (i >= n) return;
        float4 v = *(const float4*)(src + i);
        __half2 p0, p1;
        p0.x = __float2half_rn(v.x); p0.y = __float2half_rn(v.y);
        p1.x = __float2half_rn(v.z); p1.y = __float2half_rn(v.w);
        ((__half2*)(hi + i))[0] = p0;
        ((__half2*)(hi + i))[1] = p1;
        return;
    }
    const float* src; bf16* hi; bf16* lo; int n;
    switch (blockIdx.y) {
        case 0: src = s0; hi = h0; lo = l0; n = n0; break;
        case 1: src = s1; hi = h1; lo = l1; n = n1; break;
        default: src = s2; hi = h2; lo = l2; n = n2; break;
    }
    if (i >= n) return;
    float4 v = *(const float4*)(src + i);
    uint32_t hh, ll;
    split2u(v.x, v.y, hh, ll);
    ((uint32_t*)(hi + i))[0] = hh; ((uint32_t*)(lo + i))[0] = ll;
    split2u(v.z, v.w, hh, ll);
    ((uint32_t*)(hi + i))[1] = hh; ((uint32_t*)(lo + i))[1] = ll;
}

// ---------------------------------------------------------------------------
// Embedding
// ---------------------------------------------------------------------------
__global__ void embed_kernel(const int* __restrict__ idx,
                             const float* __restrict__ wte,
                             const float* __restrict__ wpe,
                             float* __restrict__ x) {
    int token = blockIdx.x;
    int t = token % TT;
    int id = idx[token];
    const float4* src = (const float4*)(wte + (size_t)id * DD);
    const float4* pos = (const float4*)(wpe + (size_t)t * DD);
    float4* dst = (float4*)(x + (size_t)token * DD);
    for (int i = threadIdx.x; i < DD / 4; i += blockDim.x) {
        float4 a = src[i], b = pos[i];
        dst[i] = make_float4(a.x + b.x, a.y + b.y, a.z + b.z, a.w + b.w);
    }
}

// ---------------------------------------------------------------------------
// LayerNorm over D=1024 -> 16-bit hi/lo (bf16 when h16=0, fp16 when h16=1)
// ---------------------------------------------------------------------------
__global__ __launch_bounds__(256) void ln_split_kernel(const float* __restrict__ x,
                                                       const float* __restrict__ sc,
                                                       const float* __restrict__ bi,
                                                       bf16* __restrict__ ohi,
                                                       bf16* __restrict__ olo,
                                                       int h16) {
    int token = blockIdx.x;
    const float4* xp = (const float4*)(x + (size_t)token * DD);
    float4 v = xp[threadIdx.x];
    float s = v.x + v.y + v.z + v.w;
    float q = v.x * v.x + v.y * v.y + v.z * v.z + v.w * v.w;
#pragma unroll
    for (int o = 16; o; o >>= 1) {
        s += __shfl_xor_sync(0xffffffffu, s, o);
        q += __shfl_xor_sync(0xffffffffu, q, o);
    }
    __shared__ float ss[8], sq[8];
    int w = threadIdx.x >> 5, l = threadIdx.x & 31;
    if (l == 0) { ss[w] = s; sq[w] = q; }
    __syncthreads();
    if (w == 0) {
        s = (l < 8) ? ss[l] : 0.f;
        q = (l < 8) ? sq[l] : 0.f;
#pragma unroll
        for (int o = 4; o; o >>= 1) {
            s += __shfl_xor_sync(0xffffffffu, s, o);
            q += __shfl_xor_sync(0xffffffffu, q, o);
        }
        if (l == 0) { ss[0] = s; sq[0] = q; }
    }
    __syncthreads();
    float mu  = ss[0] * (1.f / DD);
    float var = sq[0] * (1.f / DD) - mu * mu;
    float inv = rsqrtf(var + 1e-5f);
    float4 sv = ((const float4*)sc)[threadIdx.x];
    float4 bv = ((const float4*)bi)[threadIdx.x];
    float r0 = (v.x - mu) * inv * sv.x + bv.x;
    float r1 = (v.y - mu) * inv * sv.y + bv.y;
    float r2 = (v.z - mu) * inv * sv.z + bv.z;
    float r3 = (v.w - mu) * inv * sv.w + bv.w;
    size_t o = (size_t)token * DD + threadIdx.x * 4;
    uint32_t hh, ll;
    if (h16) {
        split2h(r0, r1, hh, ll);
        ((uint32_t*)(ohi + o))[0] = hh; ((uint32_t*)(olo + o))[0] = ll;
        split2h(r2, r3, hh, ll);
        ((uint32_t*)(ohi + o))[1] = hh; ((uint32_t*)(olo + o))[1] = ll;
    } else {
        split2u(r0, r1, hh, ll);
        ((uint32_t*)(ohi + o))[0] = hh; ((uint32_t*)(olo + o))[0] = ll;
        split2u(r2, r3, hh, ll);
        ((uint32_t*)(ohi + o))[1] = hh; ((uint32_t*)(olo + o))[1] = ll;
    }
}

// ---------------------------------------------------------------------------
#define FLAG_BIAS  1
#define FLAG_RES   2
#define FLAG_GELU  4
#define FLAG_SPLIT 8   // write C as fp16 hi/lo (consumed by fp16 2-pass GEMM)

__device__ __forceinline__ float gelu_exact(float v) {
    return 0.5f * v * (1.f + erff(v * 0.70710678118654752f));
}

// ---------------------------------------------------------------------------
// bf16 3-pass GEMM NT (trunk): CTA (MF*32)x128, warp (MF*16)x32, BK=32.
// ---------------------------------------------------------------------------
template<int MF>
__global__ __launch_bounds__(256) void gemm3t(const bf16* __restrict__ Ah,
                                              const bf16* __restrict__ Al,
                                              const bf16* __restrict__ Bh,
                                              const bf16* __restrict__ Bl,
                                              const float* __restrict__ bias,
                                              const float* res,
                                              float* C, bf16* Chi, bf16* Clo,
                                              int M, int N, int K, int flags) {
    constexpr int BMT   = MF * 32;
    constexpr int TILEA = BMT * 64;
    constexpr int TILEBB = 8192;
    constexpr int BUFB  = 2 * TILEA + 2 * TILEBB;
    constexpr int NCHUNK = (2 * BMT * 4 + 2 * 512) / 256;

    extern __shared__ __align__(16) bf16 sm[];
    int tid = threadIdx.x;
    int warp = tid >> 5, lane = tid & 31;
    int bm = blockIdx.y * BMT, bn = blockIdx.x * BN;
    int wm = (warp >> 2) * (MF * 16);
    int wn = (warp & 3) * 32;

    uint32_t smbase = (uint32_t)__cvta_generic_to_shared(sm);

    float acc[MF][4][4];
#pragma unroll
    for (int i = 0; i < MF; i++)
#pragma unroll
        for (int j = 0; j < 4; j++)
#pragma unroll
            for (int r = 0; r < 4; r++) acc[i][j][r] = 0.f;

    int a_r = ((lane >> 3) & 1) * 8 + (lane & 7);
    int a_c = (lane >> 4) * 8;
    int b_r = (lane >> 4) * 8 + (lane & 7);
    int b_c = ((lane >> 3) & 1) * 8;

    const bf16* srcA[2] = { Ah, Al };
    const bf16* srcB[2] = { Bh, Bl };

    auto stage = [&](int s_idx, int buf) {
        int k0 = s_idx * BK;
        uint32_t bufoff = smbase + (uint32_t)(buf * BUFB);
#pragma unroll
        for (int i = 0; i < NCHUNK; i++) {
            int cid = tid + i * 256;
            if (cid < 2 * BMT * 4) {
                int arr = cid / (BMT * 4);
                int sub = cid - arr * (BMT * 4);
                int row = sub >> 2;
                int c = sub & 3;
                const bf16* src = srcA[arr] + (size_t)(bm + row) * K + k0 + c * 8;
                cp16(bufoff + (uint32_t)(arr * TILEA) + swz(row, c), src);
            } else {
                int cidB = cid - 2 * BMT * 4;
                int arr = cidB >> 9;
                int sub = cidB & 511;
                int row = sub >> 2;
                int c = sub & 3;
                const bf16* src = srcB[arr] + (size_t)(bn + row) * K + k0 + c * 8;
                cp16(bufoff + (uint32_t)(2 * TILEA + arr * TILEBB) + swz(row, c), src);
            }
        }
        asm volatile("cp.async.commit_group;\n");
    };

    int S = K / BK;
    stage(0, 0);
    stage(1, 1);

    for (int s = 0; s < S; s++) {
        int buf = s - (s / NSTAGE) * NSTAGE;
        if (s == S - 1) asm volatile("cp.async.wait_group 0;\n");
        else            asm volatile("cp.async.wait_group 1;\n");
        __syncthreads();
        if (s + 2 < S) stage(s + 2, (s + 2) % NSTAGE);

        uint32_t offAh = smbase + (uint32_t)(buf * BUFB);
        uint32_t offAl = offAh + TILEA;
        uint32_t offBh = offAl + TILEA;
        uint32_t offBl = offBh + TILEBB;

#pragma unroll
        for (int ks = 0; ks < BK; ks += 16) {
            uint32_t ah[MF][4], al[MF][4], bh[4][2], bl[4][2];
#pragma unroll
            for (int mf = 0; mf < MF; mf++) {
                int row = wm + mf * 16 + a_r;
                ldm_x4(ah[mf][0], ah[mf][1], ah[mf][2], ah[mf][3],
                       offAh + swz(row, (ks + a_c) >> 3));
            }
#pragma unroll
            for (int p = 0; p < 2; p++) {
                int row = wn + p * 16 + b_r;
                uint32_t r0, r1, r2, r3;
                ldm_x4(r0, r1, r2, r3, offBh + swz(row, (ks + b_c) >> 3));
                bh[2 * p][0] = r0; bh[2 * p][1] = r1;
                bh[2 * p + 1][0] = r2; bh[2 * p + 1][1] = r3;
            }
#pragma unroll
            for (int mf = 0; mf < MF; mf++)
#pragma unroll
                for (int nf = 0; nf < 4; nf++)
                    mma16816(acc[mf][nf], ah[mf], bh[nf]);

#pragma unroll
            for (int p = 0; p < 2; p++) {
                int row = wn + p * 16 + b_r;
                uint32_t r0, r1, r2, r3;
                ldm_x4(r0, r1, r2, r3, offBl + swz(row, (ks + b_c) >> 3));
                bl[2 * p][0] = r0; bl[2 * p][1] = r1;
                bl[2 * p + 1][0] = r2; bl[2 * p + 1][1] = r3;
            }
#pragma unroll
            for (int mf = 0; mf < MF; mf++)
#pragma unroll
                for (int nf = 0; nf < 4; nf++)
                    mma16816(acc[mf][nf], ah[mf], bl[nf]);

#pragma unroll
            for (int mf = 0; mf < MF; mf++) {
                int row = wm + mf * 16 + a_r;
                ldm_x4(al[mf][0], al[mf][1], al[mf][2], al[mf][3],
                       offAl + swz(row, (ks + a_c) >> 3));
            }
#pragma unroll
            for (int mf = 0; mf < MF; mf++)
#pragma unroll
                for (int nf = 0; nf < 4; nf++)
                    mma16816(acc[mf][nf], al[mf], bh[nf]);
        }
    }

    int gid = lane >> 2, tg = lane & 3;
#pragma unroll
    for (int mf = 0; mf < MF; mf++) {
#pragma unroll
        for (int half = 0; half < 2; half++) {
            int row = bm + wm + mf * 16 + half * 8 + gid;
#pragma unroll
            for (int nf = 0; nf < 4; nf++) {
                int col = bn + wn + nf * 8 + tg * 2;
                float2 o;
                o.x = acc[mf][nf][half * 2 + 0];
                o.y = acc[mf][nf][half * 2 + 1];
                if (flags & FLAG_BIAS) { o.x += bias[col]; o.y += bias[col + 1]; }
                if (flags & FLAG_GELU) { o.x = gelu_exact(o.x); o.y = gelu_exact(o.y); }
                if (flags & FLAG_RES) {
                    float2 r = *(const float2*)(res + (size_t)row * N + col);
                    o.x += r.x; o.y += r.y;
                }
                if (flags & FLAG_SPLIT) {
                    size_t off = (size_t)row * N + col;
                    uint32_t hh, ll;
                    split2h(o.x, o.y, hh, ll);   // fp16 hi/lo for 2-pass consumer
                    *(uint32_t*)(Chi + off) = hh;
                    *(uint32_t*)(Clo + off) = ll;
                } else {
                    *(float2*)(C + (size_t)row * N + col) = o;
                }
            }
        }
    }
}

// ---------------------------------------------------------------------------
// fp16 2-pass GEMM NT: D = Ah*Bh + Al*Bh  (A split fp16, B single fp16).
// ---------------------------------------------------------------------------
template<int MF>
__global__ __launch_bounds__(256) void gemm2h(const __half* __restrict__ Ah,
                                              const __half* __restrict__ Al,
                                              const __half* __restrict__ Bh,
                                              const float* __restrict__ bias,
                                              const float* res,
                                              float* C,
                                              int M, int N, int K, int flags) {
    constexpr int BMT   = MF * 32;
    constexpr int TILEA = BMT * 64;
    constexpr int TILEBB = 8192;
    constexpr int BUFB  = 2 * TILEA + TILEBB;
    constexpr int NCHUNK = (2 * BMT * 4 + 512) / 256;

    extern __shared__ __align__(16) bf16 sm[];
    int tid = threadIdx.x;
    int warp = tid >> 5, lane = tid & 31;
    int bm = blockIdx.y * BMT, bn = blockIdx.x * BN;
    int wm = (warp >> 2) * (MF * 16);
    int wn = (warp & 3) * 32;

    uint32_t smbase = (uint32_t)__cvta_generic_to_shared(sm);

    float acc[MF][4][4];
#pragma unroll
    for (int i = 0; i < MF; i++)
#pragma unroll
        for (int j = 0; j < 4; j++)
#pragma unroll
            for (int r = 0; r < 4; r++) acc[i][j][r] = 0.f;

    int a_r = ((lane >> 3) & 1) * 8 + (lane & 7);
    int a_c = (lane >> 4) * 8;
    int b_r = (lane >> 4) * 8 + (lane & 7);
    int b_c = ((lane >> 3) & 1) * 8;

    const __half* srcA[2] = { Ah, Al };

    auto stage = [&](int s_idx, int buf) {
        int k0 = s_idx * BK;
        uint32_t bufoff = smbase + (uint32_t)(buf * BUFB);
#pragma unroll
        for (int i = 0; i < NCHUNK; i++) {
            int cid = tid + i * 256;
            if (cid < 2 * BMT * 4) {
                int arr = cid / (BMT * 4);
                int sub = cid - arr * (BMT * 4);
                int row = sub >> 2;
                int c = sub & 3;
                const __half* src = srcA[arr] + (size_t)(bm + row) * K + k0 + c * 8;
                cp16(bufoff + (uint32_t)(arr * TILEA) + swz(row, c), src);
            } else {
                int sub = cid - 2 * BMT * 4;
                int row = sub >> 2;
                int c = sub & 3;
                const __half* src = Bh + (size_t)(bn + row) * K + k0 + c * 8;
                cp16(bufoff + (uint32_t)(2 * TILEA) + swz(row, c), src);
            }
        }
        asm volatile("cp.async.commit_group;\n");
    };

    int S = K / BK;
    stage(0, 0);
    stage(1, 1);

    for (int s = 0; s < S; s++) {
        int buf = s - (s / NSTAGE) * NSTAGE;
        if (s == S - 1) asm volatile("cp.async.wait_group 0;\n");
        else            asm volatile("cp.async.wait_group 1;\n");
        __syncthreads();
        if (s + 2 < S) stage(s + 2, (s + 2) % NSTAGE);

        uint32_t offAh = smbase + (uint32_t)(buf * BUFB);
        uint32_t offAl = offAh + TILEA;
        uint32_t offB  = offAl + TILEA;

#pragma unroll
        for (int ks = 0; ks < BK; ks += 16) {
            uint32_t ah[MF][4], al[MF][4], bh[4][2];
#pragma unroll
            for (int mf = 0; mf < MF; mf++) {
                int row = wm + mf * 16 + a_r;
                ldm_x4(ah[mf][0], ah[mf][1], ah[mf][2], ah[mf][3],
                       offAh + swz(row, (ks + a_c) >> 3));
            }
#pragma unroll
            for (int p = 0; p < 2; p++) {
                int row = wn + p * 16 + b_r;
                uint32_t r0, r1, r2, r3;
                ldm_x4(r0, r1, r2, r3, offB + swz(row, (ks + b_c) >> 3));
                bh[2 * p][0] = r0; bh[2 * p][1] = r1;
                bh[2 * p + 1][0] = r2; bh[2 * p + 1][1] = r3;
            }
#pragma unroll
            for (int mf = 0; mf < MF; mf++)
#pragma unroll
                for (int nf = 0; nf < 4; nf++)
                    mma16816h(acc[mf][nf], ah[mf], bh[nf]);

#pragma unroll
            for (int mf = 0; mf < MF; mf++) {
                int row = wm + mf * 16 + a_r;
                ldm_x4(al[mf][0], al[mf][1], al[mf][2], al[mf][3],
                       offAl + swz(row, (ks + a_c) >> 3));
            }
#pragma unroll
            for (int mf = 0; mf < MF; mf++)
#pragma unroll
                for (int nf = 0; nf < 4; nf++)
                    mma16816h(acc[mf][nf], al[mf], bh[nf]);
        }
    }

    int gid = lane >> 2, tg = lane & 3;
#pragma unroll
    for (int mf = 0; mf < MF; mf++) {
#pragma unroll
        for (int half = 0; half < 2; half++) {
            int row = bm + wm + mf * 16 + half * 8 + gid;
#pragma unroll
            for (int nf = 0; nf < 4; nf++) {
                int col = bn + wn + nf * 8 + tg * 2;
                float2 o;
                o.x = acc[mf][nf][half * 2 + 0];
                o.y = acc[mf][nf][half * 2 + 1];
                if (flags & FLAG_BIAS) { o.x += bias[col]; o.y += bias[col + 1]; }
                if (flags & FLAG_RES) {
                    float2 r = *(const float2*)(res + (size_t)row * N + col);
                    o.x += r.x; o.y += r.y;
                }
                *(float2*)(C + (size_t)row * N + col) = o;
            }
        }
    }
}

// Dynamic smem sizes
#define GSM3_MF2 (NSTAGE * (2 * 64 * 64 + 2 * 8192))    // 73728
#define GSM3_MF4 (NSTAGE * (2 * 128 * 64 + 2 * 8192))   // 98304
#define GSM2_MF2 (NSTAGE * (2 * 64 * 64 + 8192))        // 49152
#define GSM2_MF4 (NSTAGE * (2 * 128 * 64 + 8192))       // 73728

// ---------------------------------------------------------------------------
// Causal attention via mma.sync (flash-attention, bf16-split fp32-accurate).
// ---------------------------------------------------------------------------
__global__ __launch_bounds__(256) void attn_mma(const float* __restrict__ qkv,
                                                bf16* __restrict__ yhi,
                                                bf16* __restrict__ ylo) {
    int b = blockIdx.z, h = blockIdx.y;
    int bx = gridDim.x - 1 - blockIdx.x;
    int tid = threadIdx.x;
    int warp = tid >> 5, lane = tid & 31;
    int g = lane >> 2, t4 = lane & 3;
    int q0w = bx * AQ + warp * 16;

    __shared__ __align__(16) bf16 Kh_s[AKT * LDV];
    __shared__ __align__(16) bf16 Kl_s[AKT * LDV];
    __shared__ __align__(16) bf16 Vh_s[AKT * LDV];
    __shared__ __align__(16) bf16 Vl_s[AKT * LDV];
    uint32_t aKh = (uint32_t)__cvta_generic_to_shared(Kh_s);
    uint32_t aKl = (uint32_t)__cvta_generic_to_shared(Kl_s);
    uint32_t aVh = (uint32_t)__cvta_generic_to_shared(Vh_s);
    uint32_t aVl = (uint32_t)__cvta_generic_to_shared(Vl_s);

    uint32_t qh[4][4], ql[4][4];
    {
        const float* qbase = qkv + (size_t)(b * TT) * (3 * DD) + h * HDIM;
        const float* r0p = qbase + (size_t)(q0w + g) * (3 * DD);
        const float* r1p = qbase + (size_t)(q0w + g + 8) * (3 * DD);
#pragma unroll
        for (int c = 0; c < 4; c++) {
            float2 v00 = *(const float2*)(r0p + c * 16 + 2 * t4);
            float2 v10 = *(const float2*)(r1p + c * 16 + 2 * t4);
            float2 v01 = *(const float2*)(r0p + c * 16 + 2 * t4 + 8);
            float2 v11 = *(const float2*)(r1p + c * 16 + 2 * t4 + 8);
            split2u(v00.x * 0.125f, v00.y * 0.125f, qh[c][0], ql[c][0]);
            split2u(v10.x * 0.125f, v10.y * 0.125f, qh[c][1], ql[c][1]);
            split2u(v01.x * 0.125f, v01.y * 0.125f, qh[c][2], ql[c][2]);
            split2u(v11.x * 0.125f, v11.y * 0.125f, qh[c][3], ql[c][3]);
        }
    }

    float O[8][4];
#pragma unroll
    for (int j = 0; j < 8; j++)
#pragma unroll
        for (int r = 0; r < 4; r++) O[j][r] = 0.f;
    float m0 = NEGINF, m1 = NEGINF, l0 = 0.f, l1 = 0.f;

    int b_r = (lane >> 4) * 8 + (lane & 7);
    int b_c = ((lane >> 3) & 1) * 8;
    int v_r = (lane & 7) + ((lane >> 3) & 1) * 8;
    int v_c = (lane >> 4) * 8;

    const float* kb = qkv + (size_t)(b * TT) * (3 * DD) + DD + h * HDIM;
    const float* vb = kb + DD;

    int ntiles = bx * 2 + 2;
    for (int tile = 0; tile < ntiles; tile++) {
        int kt = tile * AKT;
        __syncthreads();
#pragma unroll
        for (int i = 0; i < 8; i++) {
            int cid = tid + i * 256;
            int kk = cid >> 5;
            int d2 = (cid & 31) * 2;
            const float* kr = kb + (size_t)(kt + kk) * (3 * DD) + d2;
            const float* vr = vb + (size_t)(kt + kk) * (3 * DD) + d2;
            float2 kv = *(const float2*)kr;
            float2 vv = *(const float2*)vr;
            uint32_t hh, ll;
            split2u(kv.x, kv.y, hh, ll);
            *(uint32_t*)(Kh_s + kk * LDV + d2) = hh;
            *(uint32_t*)(Kl_s + kk * LDV + d2) = ll;
            split2u(vv.x, vv.y, hh, ll);
            *(uint32_t*)(Vh_s + kk * LDV + d2) = hh;
            *(uint32_t*)(Vl_s + kk * LDV + d2) = ll;
        }
        __syncthreads();

        if (kt > q0w + 15) continue;

        float S[8][4];
#pragma unroll
        for (int j = 0; j < 8; j++)
#pragma unroll
            for (int r = 0; r < 4; r++) S[j][r] = 0.f;

#pragma unroll
        for (int c = 0; c < 4; c++) {
            uint32_t kf[8][2];
#pragma unroll
            for (int p = 0; p < 4; p++) {
                uint32_t r0, r1, r2, r3;
                ldm_x4(r0, r1, r2, r3, aKh + (uint32_t)((16 * p + b_r) * LDV + 16 * c + b_c) * 2);
                kf[2 * p][0] = r0; kf[2 * p][1] = r1;
                kf[2 * p + 1][0] = r2; kf[2 * p + 1][1] = r3;
            }
#pragma unroll
            for (int j = 0; j < 8; j++) mma16816(S[j], qh[c], kf[j]);
#pragma unroll
            for (int j = 0; j < 8; j++) mma16816(S[j], ql[c], kf[j]);
#pragma unroll
            for (int p = 0; p < 4; p++) {
                uint32_t r0, r1, r2, r3;
                ldm_x4(r0, r1, r2, r3, aKl + (uint32_t)((16 * p + b_r) * LDV + 16 * c + b_c) * 2);
                kf[2 * p][0] = r0; kf[2 * p][1] = r1;
                kf[2 * p + 1][0] = r2; kf[2 * p + 1][1] = r3;
            }
#pragma unroll
            for (int j = 0; j < 8; j++) mma16816(S[j], qh[c], kf[j]);
        }

        if (kt + AKT - 1 > q0w) {
            int row0 = q0w + g, row1 = q0w + g + 8;
#pragma unroll
            for (int j = 0; j < 8; j++) {
                int col = kt + 8 * j + 2 * t4;
                if (col > row0)     S[j][0] = NEGINF;
                if (col + 1 > row0) S[j][1] = NEGINF;
                if (col > row1)     S[j][2] = NEGINF;
                if (col + 1 > row1) S[j][3] = NEGINF;
            }
        }

        float mx0 = NEGINF, mx1 = NEGINF;
#pragma unroll
        for (int j = 0; j < 8; j++) {
            mx0 = fmaxf(mx0, fmaxf(S[j][0], S[j][1]));
            mx1 = fmaxf(mx1, fmaxf(S[j][2], S[j][3]));
        }
        mx0 = fmaxf(mx0, __shfl_xor_sync(0xffffffffu, mx0, 1));
        mx0 = fmaxf(mx0, __shfl_xor_sync(0xffffffffu, mx0, 2));
        mx1 = fmaxf(mx1, __shfl_xor_sync(0xffffffffu, mx1, 1));
        mx1 = fmaxf(mx1, __shfl_xor_sync(0xffffffffu, mx1, 2));
        float m0n = fmaxf(m0, mx0), m1n = fmaxf(m1, mx1);
        float c0 = __expf(m0 - m0n), c1 = __expf(m1 - m1n);
        float s0 = 0.f, s1 = 0.f;
#pragma unroll
        for (int j = 0; j < 8; j++) {
            S[j][0] = __expf(S[j][0] - m0n);
            S[j][1] = __expf(S[j][1] - m0n);
            S[j][2] = __expf(S[j][2] - m1n);
            S[j][3] = __expf(S[j][3] - m1n);
            s0 += S[j][0] + S[j][1];
            s1 += S[j][2] + S[j][3];
        }
        s0 += __shfl_xor_sync(0xffffffffu, s0, 1);
        s0 += __shfl_xor_sync(0xffffffffu, s0, 2);
        s1 += __shfl_xor_sync(0xffffffffu, s1, 1);
        s1 += __shfl_xor_sync(0xffffffffu, s1, 2);
        l0 = l0 * c0 + s0;
        l1 = l1 * c1 + s1;
        m0 = m0n; m1 = m1n;
#pragma unroll
        for (int j = 0; j < 8; j++) {
            O[j][0] *= c0; O[j][1] *= c0;
            O[j][2] *= c1; O[j][3] *= c1;
        }

#pragma unroll
        for (int kk = 0; kk < 4; kk++) {
            uint32_t ph[4], pl[4];
            split2u(S[2 * kk][0],     S[2 * kk][1],     ph[0], pl[0]);
            split2u(S[2 * kk][2],     S[2 * kk][3],     ph[1], pl[1]);
            split2u(S[2 * kk + 1][0], S[2 * kk + 1][1], ph[2], pl[2]);
            split2u(S[2 * kk + 1][2], S[2 * kk + 1][3], ph[3], pl[3]);

            uint32_t vf[8][2];
#pragma unroll
            for (int ds = 0; ds < 4; ds++) {
                uint32_t r0, r1, r2, r3;
                ldm_x4_t(r0, r1, r2, r3, aVh + (uint32_t)((16 * kk + v_r) * LDV + 16 * ds + v_c) * 2);
                vf[2 * ds][0] = r0; vf[2 * ds][1] = r1;
                vf[2 * ds + 1][0] = r2; vf[2 * ds + 1][1] = r3;
            }
#pragma unroll
            for (int j = 0; j < 8; j++) mma16816(O[j], ph, vf[j]);
#pragma unroll
            for (int j = 0; j < 8; j++) mma16816(O[j], pl, vf[j]);
#pragma unroll
            for (int ds = 0; ds < 4; ds++) {
                uint32_t r0, r1, r2, r3;
                ldm_x4_t(r0, r1, r2, r3, aVl + (uint32_t)((16 * kk + v_r) * LDV + 16 * ds + v_c) * 2);
                vf[2 * ds][0] = r0; vf[2 * ds][1] = r1;
                vf[2 * ds + 1][0] = r2; vf[2 * ds + 1][1] = r3;
            }
#pragma unroll
            for (int j = 0; j < 8; j++) mma16816(O[j], ph, vf[j]);
        }
    }

    float i0 = 1.f / l0, i1 = 1.f / l1;
    size_t off0 = (size_t)(b * TT + q0w + g) * DD + h * HDIM + 2 * t4;
    size_t off1 = (size_t)(b * TT + q0w + g + 8) * DD + h * HDIM + 2 * t4;
#pragma unroll
    for (int j = 0; j < 8; j++) {
        uint32_t hh, ll;
        split2u(O[j][0] * i0, O[j][1] * i0, hh, ll);
        *(uint32_t*)(yhi + off0 + 8 * j) = hh;
        *(uint32_t*)(ylo + off0 + 8 * j) = ll;
        split2u(O[j][2] * i1, O[j][3] * i1, hh, ll);
        *(uint32_t*)(yhi + off1 + 8 * j) = hh;
        *(uint32_t*)(ylo + off1 + 8 * j) = ll;
    }
}

// ---------------------------------------------------------------------------
// Host launcher
// ---------------------------------------------------------------------------
extern "C" void kernel_launch(void* const* d_in, const int* in_sizes, int n_in,
                              void* d_out, int out_size) {
    const int*   idx    = (const int*)  d_in[0];
    const float* wte    = (const float*)d_in[1];
    const float* wpe    = (const float*)d_in[2];
    const float* ln1_s  = (const float*)d_in[3];
    const float* ln1_b  = (const float*)d_in[4];
    const float* qkv_w  = (const float*)d_in[5];
    const float* proj_w = (const float*)d_in[6];
    const float* ln2_s  = (const float*)d_in[7];
    const float* ln2_b  = (const float*)d_in[8];
    const float* fc_w   = (const float*)d_in[9];
    const float* fc_b   = (const float*)d_in[10];
    const float* fc2_w  = (const float*)d_in[11];
    const float* fc2_b  = (const float*)d_in[12];
    const float* lnf_s  = (const float*)d_in[13];
    const float* lnf_b  = (const float*)d_in[14];
    const float* lm_w   = (const float*)d_in[15];
    float* out = (float*)d_out;

    float *x, *qkv;
    bf16 *h_hi, *h_lo, *y_hi, *y_lo, *gg_hi, *gg_lo;
    bf16 *qw_hi, *qw_lo, *pw_hi, *pw_lo, *fw_hi, *fw_lo, *f2_hi, *lw_hi;
    cudaGetSymbolAddress((void**)&x,     g_x);
    cudaGetSymbolAddress((void**)&qkv,   g_qkv);
    cudaGetSymbolAddress((void**)&h_hi,  g_h_hi);   cudaGetSymbolAddress((void**)&h_lo,  g_h_lo);
    cudaGetSymbolAddress((void**)&y_hi,  g_y_hi);   cudaGetSymbolAddress((void**)&y_lo,  g_y_lo);
    cudaGetSymbolAddress((void**)&gg_hi, g_g_hi);   cudaGetSymbolAddress((void**)&gg_lo, g_g_lo);
    cudaGetSymbolAddress((void**)&qw_hi, g_qkvw_hi); cudaGetSymbolAddress((void**)&qw_lo, g_qkvw_lo);
    cudaGetSymbolAddress((void**)&pw_hi, g_projw_hi); cudaGetSymbolAddress((void**)&pw_lo, g_projw_lo);
    cudaGetSymbolAddress((void**)&fw_hi, g_fcw_hi);  cudaGetSymbolAddress((void**)&fw_lo, g_fcw_lo);
    cudaGetSymbolAddress((void**)&f2_hi, g_fc2w_hi);
    cudaGetSymbolAddress((void**)&lw_hi, g_lmw_hi);

    cudaFuncSetAttribute(gemm3t<2>, cudaFuncAttributeMaxDynamicSharedMemorySize, GSM3_MF2);
    cudaFuncSetAttribute(gemm3t<4>, cudaFuncAttributeMaxDynamicSharedMemorySize, GSM3_MF4);
    cudaFuncSetAttribute(gemm2h<2>, cudaFuncAttributeMaxDynamicSharedMemorySize, GSM2_MF2);
    cudaFuncSetAttribute(gemm2h<4>, cudaFuncAttributeMaxDynamicSharedMemorySize, GSM2_MF4);

    embed_kernel<<<MM, 256>>>(idx, wte, wpe, x);

    {
        int nq = LL * 3 * DD * DD, np = LL * DD * DD;
        int nf = LL * 4 * DD * DD, n2 = LL * 4 * DD * DD, nl = VV * DD;
        int maxn = nf;
        dim3 grid((maxn / 4 + 255) / 256, 5);
        wsplit_all<<<grid, 256>>>(qkv_w,  qw_hi, qw_lo, nq,
                                  proj_w, pw_hi, pw_lo, np,
                                  fc_w,   fw_hi, fw_lo, nf,
                                  fc2_w,  f2_hi, n2,
                                  lm_w,   lw_hi, nl);
    }

    for (int l = 0; l < LL; l++) {
        bf16* qwh = qw_hi + (size_t)l * 3 * DD * DD;  bf16* qwl = qw_lo + (size_t)l * 3 * DD * DD;
        bf16* pwh = pw_hi + (size_t)l * DD * DD;      bf16* pwl = pw_lo + (size_t)l * DD * DD;
        bf16* fwh = fw_hi + (size_t)l * 4 * DD * DD;  bf16* fwl = fw_lo + (size_t)l * 4 * DD * DD;
        const __half* f2h = (const __half*)(f2_hi + (size_t)l * 4 * DD * DD);
        const float* fb  = fc_b  + (size_t)l * 4 * DD;
        const float* f2b = fc2_b + (size_t)l * DD;

        ln_split_kernel<<<MM, 256>>>(x, ln1_s + l * DD, ln1_b + l * DD, h_hi, h_lo, 0);
        // qkv: bf16 3-pass, MF=2, grid 24x32 = 768
        gemm3t<2><<<dim3(3 * DD / BN, MM / 64), 256, GSM3_MF2>>>(h_hi, h_lo, qwh, qwl,
            nullptr, nullptr, qkv, nullptr, nullptr, MM, 3 * DD, DD, 0);
        attn_mma<<<dim3(TT / AQ, HH, BB), 256>>>(qkv, y_hi, y_lo);
        // proj: bf16 3-pass, MF=2, grid 8x32 = 256
        gemm3t<2><<<dim3(DD / BN, MM / 64), 256, GSM3_MF2>>>(y_hi, y_lo, pwh, pwl,
            nullptr, x, x, nullptr, nullptr, MM, DD, DD, FLAG_RES);
        ln_split_kernel<<<MM, 256>>>(x, ln2_s + l * DD, ln2_b + l * DD, h_hi, h_lo, 0);
        // fc: bf16 3-pass, MF=4, grid 32x16 = 512; epilogue writes g as fp16 hi/lo
        gemm3t<4><<<dim3(4 * DD / BN, MM / 128), 256, GSM3_MF4>>>(h_hi, h_lo, fwh, fwl,
            fb, nullptr, nullptr, gg_hi, gg_lo, MM, 4 * DD, DD, FLAG_BIAS | FLAG_GELU | FLAG_SPLIT);
        // fc2: fp16 2-pass (A=g split fp16, B single fp16), MF=2, grid 8x32 = 256
        gemm2h<2><<<dim3(DD / BN, MM / 64), 256, GSM2_MF2>>>(
            (const __half*)gg_hi, (const __half*)gg_lo, f2h,
            f2b, x, x, MM, DD, 4 * DD, FLAG_BIAS | FLAG_RES);
    }

    // lnf -> fp16 hi/lo
    ln_split_kernel<<<MM, 256>>>(x, lnf_s, lnf_b, h_hi, h_lo, 1);
    // lm: fp16 2-pass, MF=4, grid 250x16 = 4000
    gemm2h<4><<<dim3(VV / BN, MM / 128), 256, GSM2_MF4>>>(
        (const __half*)h_hi, (const __half*)h_lo, (const __half*)lw_hi,
        nullptr, nullptr, out, MM, VV, DD, 0);
}